// round 7
// baseline (speedup 1.0000x reference)
#include <cuda_runtime.h>
#include <cuda_bf16.h>
#include <math.h>
#include <math_constants.h>
#include <cstdint>

#define HDIM 256
#define MAXB 1024
#define MAXN 32768

// ---------------------------------------------------------------------------
// Scratch (__device__ globals; no dynamic allocation allowed)
// ---------------------------------------------------------------------------
__device__ float g_q[(size_t)MAXB * HDIM];
__device__ float g_k[(size_t)MAXN * HDIM];
__device__ float g_v[(size_t)MAXN * HDIM];
__device__ __nv_bfloat16 g_ahi[(size_t)MAXN * HDIM];   // split of social_ht
__device__ __nv_bfloat16 g_alo[(size_t)MAXN * HDIM];
__device__ __nv_bfloat16 g_wkt_hi[HDIM * HDIM];        // W^T splits: [n][k], k contiguous
__device__ __nv_bfloat16 g_wkt_lo[HDIM * HDIM];
__device__ __nv_bfloat16 g_wvt_hi[HDIM * HDIM];
__device__ __nv_bfloat16 g_wvt_lo[HDIM * HDIM];

// ---------------------------------------------------------------------------
// Prep: split fp32 -> (hi, lo) bf16 pair.  a = hi + lo to ~16 mantissa bits.
// ---------------------------------------------------------------------------
__global__ void __launch_bounds__(256) split_a_kernel(
    const float* __restrict__ src, __nv_bfloat16* __restrict__ hi, __nv_bfloat16* __restrict__ lo)
{
    const size_t base = ((size_t)blockIdx.x * 256 + threadIdx.x) * 8;
    float4 a = *(const float4*)(src + base);
    float4 b = *(const float4*)(src + base + 4);
    __nv_bfloat16 h[8], l[8];
    float v[8] = {a.x, a.y, a.z, a.w, b.x, b.y, b.z, b.w};
    #pragma unroll
    for (int i = 0; i < 8; i++) {
        h[i] = __float2bfloat16(v[i]);
        l[i] = __float2bfloat16(v[i] - __bfloat162float(h[i]));
    }
    *(uint4*)(hi + base) = *(const uint4*)h;
    *(uint4*)(lo + base) = *(const uint4*)l;
}

// Transpose + split both weight matrices: out[n][k] = split(W[k][n])
__global__ void __launch_bounds__(256) split_w_kernel(
    const float* __restrict__ Wk, const float* __restrict__ Wv,
    __nv_bfloat16* __restrict__ khi, __nv_bfloat16* __restrict__ klo,
    __nv_bfloat16* __restrict__ vhi, __nv_bfloat16* __restrict__ vlo)
{
    const int n = blockIdx.x, k = threadIdx.x;
    const float* W = blockIdx.y ? Wv : Wk;
    __nv_bfloat16* oh = blockIdx.y ? vhi : khi;
    __nv_bfloat16* ol = blockIdx.y ? vlo : klo;
    float a = W[k * HDIM + n];
    __nv_bfloat16 h = __float2bfloat16(a);
    oh[n * HDIM + k] = h;
    ol[n * HDIM + k] = __float2bfloat16(a - __bfloat162float(h));
}

// ---------------------------------------------------------------------------
// K/V GEMM via mma.sync.m16n8k16.bf16, cp.async double buffered.
// 512 threads, 16 warps = 4(m) x 4(n); warp tile 32x32 = 2 x 4 mma tiles.
// 3-MMA split: hi*hi + hi*lo + lo*hi.
// ---------------------------------------------------------------------------
#define KC 64                        // smem K-chunk (bf16 elems)
#define NCHUNK (HDIM / KC)           // 4
#define SROW 72                      // padded smem row stride (elems); 144 B
#define TILE_ELEMS (128 * SROW)      // per operand array
#define STAGE_ELEMS (4 * TILE_ELEMS) // Ahi, Alo, Bhi, Blo
#define SMEM_BYTES (2 * STAGE_ELEMS * 2)  // double buffered: 147456

__device__ __forceinline__ uint32_t lds32(const __nv_bfloat16* p, int elem_off) {
    return *(const uint32_t*)(p + elem_off);
}
__device__ __forceinline__ void mma_bf16(float* d, const uint32_t* a, uint32_t b0, uint32_t b1) {
    asm volatile(
        "mma.sync.aligned.m16n8k16.row.col.f32.bf16.bf16.f32 "
        "{%0,%1,%2,%3}, {%4,%5,%6,%7}, {%8,%9}, {%0,%1,%2,%3};\n"
        : "+f"(d[0]), "+f"(d[1]), "+f"(d[2]), "+f"(d[3])
        : "r"(a[0]), "r"(a[1]), "r"(a[2]), "r"(a[3]), "r"(b0), "r"(b1));
}
__device__ __forceinline__ void cp_async16(uint32_t smem_dst, const void* gsrc) {
    asm volatile("cp.async.cg.shared.global [%0], [%1], 16;\n" :: "r"(smem_dst), "l"(gsrc));
}

__global__ void __launch_bounds__(512, 1) kv_mma_kernel(
    const float* __restrict__ bk, const float* __restrict__ bv)
{
    extern __shared__ __nv_bfloat16 sm[];

    const int tid = threadIdx.x;
    const int wid = tid >> 5;
    const int lane = tid & 31;
    const int grp = lane >> 2;      // 0..7
    const int qid = lane & 3;       // 0..3
    const int warp_m = wid & 3;     // 4 warps along m (32 rows each)
    const int warp_n = wid >> 2;    // 4 warps along n (32 cols each)

    const int bn = blockIdx.x;      // n-tile (0..1)
    const int bm = blockIdx.y;      // m-tile (0..255)
    const int mat = blockIdx.z;     // 0 = K, 1 = V

    const __nv_bfloat16* gBhi = mat ? g_wvt_hi : g_wkt_hi;
    const __nv_bfloat16* gBlo = mat ? g_wvt_lo : g_wkt_lo;
    float* C = mat ? g_v : g_k;
    const float* bias = mat ? bv : bk;

    const __nv_bfloat16* gsrc[4] = {g_ahi, g_alo, gBhi, gBlo};
    const int grow[4] = {bm * 128, bm * 128, bn * 128, bn * 128};

    uint32_t smem_u32;
    {
        uint64_t t = __cvta_generic_to_shared(sm);
        smem_u32 = (uint32_t)t;
    }

    // Per-thread load geometry (2 segs of 16B per array): seg = tid + u*512
    // row = seg>>3 (0..127), cs = seg&7 (16B column segment).
    int lrow[2], lcs[2];
    #pragma unroll
    for (int u = 0; u < 2; u++) {
        int seg = u * 512 + tid;
        lrow[u] = seg >> 3;
        lcs[u] = seg & 7;
    }

    auto prefetch = [&](int s, int c) {
        uint32_t stage = smem_u32 + s * (STAGE_ELEMS * 2);
        #pragma unroll
        for (int arr = 0; arr < 4; arr++) {
            const __nv_bfloat16* src = gsrc[arr] + (size_t)grow[arr] * HDIM + c * KC;
            uint32_t dstbase = stage + arr * (TILE_ELEMS * 2);
            #pragma unroll
            for (int u = 0; u < 2; u++) {
                cp_async16(dstbase + lrow[u] * (SROW * 2) + lcs[u] * 16,
                           src + (size_t)lrow[u] * HDIM + lcs[u] * 8);
            }
        }
        asm volatile("cp.async.commit_group;\n");
    };

    float acc[2][4][4] = {};

    prefetch(0, 0);

    for (int c = 0; c < NCHUNK; c++) {
        if (c + 1 < NCHUNK) {
            prefetch((c + 1) & 1, c + 1);
            asm volatile("cp.async.wait_group 1;\n");
        } else {
            asm volatile("cp.async.wait_group 0;\n");
        }
        __syncthreads();

        const __nv_bfloat16* st = sm + (c & 1) * STAGE_ELEMS;
        const __nv_bfloat16* sAhi = st;
        const __nv_bfloat16* sAlo = st + TILE_ELEMS;
        const __nv_bfloat16* sBhi = st + 2 * TILE_ELEMS;
        const __nv_bfloat16* sBlo = st + 3 * TILE_ELEMS;

        #pragma unroll
        for (int ks = 0; ks < KC / 16; ks++) {
            const int k0 = ks * 16;
            uint32_t ahi[2][4], alo[2][4];
            #pragma unroll
            for (int mi = 0; mi < 2; mi++) {
                const int abase = (warp_m * 32 + mi * 16 + grp) * SROW + k0 + 2 * qid;
                ahi[mi][0] = lds32(sAhi, abase);
                ahi[mi][1] = lds32(sAhi, abase + 8 * SROW);
                ahi[mi][2] = lds32(sAhi, abase + 8);
                ahi[mi][3] = lds32(sAhi, abase + 8 * SROW + 8);
                alo[mi][0] = lds32(sAlo, abase);
                alo[mi][1] = lds32(sAlo, abase + 8 * SROW);
                alo[mi][2] = lds32(sAlo, abase + 8);
                alo[mi][3] = lds32(sAlo, abase + 8 * SROW + 8);
            }
            #pragma unroll
            for (int nb = 0; nb < 4; nb++) {
                const int bbase = (warp_n * 32 + nb * 8 + grp) * SROW + k0 + 2 * qid;
                uint32_t bh0 = lds32(sBhi, bbase), bh1 = lds32(sBhi, bbase + 8);
                uint32_t bl0 = lds32(sBlo, bbase), bl1 = lds32(sBlo, bbase + 8);
                #pragma unroll
                for (int mi = 0; mi < 2; mi++) {
                    mma_bf16(acc[mi][nb], ahi[mi], bh0, bh1);
                    mma_bf16(acc[mi][nb], ahi[mi], bl0, bl1);
                    mma_bf16(acc[mi][nb], alo[mi], bh0, bh1);
                }
            }
        }
        __syncthreads();   // readers done before next iteration's prefetch overwrites
    }

    // Epilogue: bias + relu, fp32 stores.
    #pragma unroll
    for (int mi = 0; mi < 2; mi++) {
        const int row = bm * 128 + warp_m * 32 + mi * 16 + grp;
        #pragma unroll
        for (int nb = 0; nb < 4; nb++) {
            const int col = bn * 128 + warp_n * 32 + nb * 8 + 2 * qid;
            float2 bz = *(const float2*)(bias + col);
            float2 o0, o1;
            o0.x = fmaxf(acc[mi][nb][0] + bz.x, 0.f);
            o0.y = fmaxf(acc[mi][nb][1] + bz.y, 0.f);
            o1.x = fmaxf(acc[mi][nb][2] + bz.x, 0.f);
            o1.y = fmaxf(acc[mi][nb][3] + bz.y, 0.f);
            *(float2*)(C + (size_t)row * HDIM + col) = o0;
            *(float2*)(C + (size_t)(row + 8) * HDIM + col) = o1;
        }
    }
}

// ---------------------------------------------------------------------------
// Q GEMM (scalar, tiny: 1024x256x256) — unchanged, known-correct.
// ---------------------------------------------------------------------------
__global__ void __launch_bounds__(256) gemm_bias_relu(
    const float* __restrict__ A, const float* __restrict__ W,
    const float* __restrict__ bias, float* __restrict__ C, float scale)
{
    __shared__ float As[16][65];
    __shared__ float Ws[16][64];
    const int tid = threadIdx.x;
    const int bm = blockIdx.y * 64, bn = blockIdx.x * 64;
    const int tx = tid & 15, ty = tid >> 4;
    const int lm = tid >> 2, lk4 = (tid & 3) * 4;
    const int lwk = tid >> 4, lwn = (tid & 15) * 4;
    const float* Arow = A + (size_t)(bm + lm) * HDIM;
    float acc[4][4] = {};
    for (int k0 = 0; k0 < HDIM; k0 += 16) {
        float4 a4 = *(const float4*)(Arow + k0 + lk4);
        float4 w4 = *(const float4*)(W + (size_t)(k0 + lwk) * HDIM + bn + lwn);
        As[lk4 + 0][lm] = a4.x; As[lk4 + 1][lm] = a4.y;
        As[lk4 + 2][lm] = a4.z; As[lk4 + 3][lm] = a4.w;
        *(float4*)&Ws[lwk][lwn] = w4;
        __syncthreads();
        #pragma unroll
        for (int kk = 0; kk < 16; kk++) {
            float a[4], w[4];
            #pragma unroll
            for (int i = 0; i < 4; i++) a[i] = As[kk][ty * 4 + i];
            #pragma unroll
            for (int j = 0; j < 4; j++) w[j] = Ws[kk][tx * 4 + j];
            #pragma unroll
            for (int i = 0; i < 4; i++)
                #pragma unroll
                for (int j = 0; j < 4; j++)
                    acc[i][j] = fmaf(a[i], w[j], acc[i][j]);
        }
        __syncthreads();
    }
    const int col = bn + tx * 4;
    float c0 = bias[col], c1 = bias[col + 1], c2 = bias[col + 2], c3 = bias[col + 3];
    #pragma unroll
    for (int i = 0; i < 4; i++) {
        const int row = bm + ty * 4 + i;
        float4 r;
        r.x = fmaxf(acc[i][0] + c0, 0.f) * scale;
        r.y = fmaxf(acc[i][1] + c1, 0.f) * scale;
        r.z = fmaxf(acc[i][2] + c2, 0.f) * scale;
        r.w = fmaxf(acc[i][3] + c3, 0.f) * scale;
        *(float4*)(C + (size_t)row * HDIM + col) = r;
    }
}

// ---------------------------------------------------------------------------
// Windowed attention — unchanged, known-correct.
// ---------------------------------------------------------------------------
__global__ void __launch_bounds__(256) attn_kernel(
    const int* __restrict__ starts, const int* __restrict__ ends, float* __restrict__ out)
{
    const int i = blockIdx.x;
    const int tid = threadIdx.x;
    const int warp = tid >> 5, lane = tid & 31;
    __shared__ float qs[HDIM];
    __shared__ float sc[64];
    __shared__ float redbuf[8];
    qs[tid] = g_q[(size_t)i * HDIM + tid];
    const int s = starts[i];
    const int nn = ends[i] - s;
    __syncthreads();
    for (int j = warp; j < nn; j += 8) {
        const float* krow = g_k + (size_t)(s + j) * HDIM;
        float acc = 0.f;
        #pragma unroll
        for (int c = 0; c < HDIM / 32; c++)
            acc = fmaf(qs[lane + 32 * c], krow[lane + 32 * c], acc);
        #pragma unroll
        for (int o = 16; o; o >>= 1) acc += __shfl_xor_sync(0xffffffffu, acc, o);
        if (lane == 0) sc[j] = acc;
    }
    __syncthreads();
    float x = -CUDART_INF_F;
    if (tid < 64) {
        x = (tid < nn) ? sc[tid] : -CUDART_INF_F;
        float m = x;
        #pragma unroll
        for (int o = 16; o; o >>= 1) m = fmaxf(m, __shfl_xor_sync(0xffffffffu, m, o));
        if (lane == 0) redbuf[warp] = m;
    }
    __syncthreads();
    const float m = fmaxf(redbuf[0], redbuf[1]);
    float p = 0.f;
    if (tid < 64) {
        p = (tid < nn) ? expf(x - m) : 0.f;
        float ssum = p;
        #pragma unroll
        for (int o = 16; o; o >>= 1) ssum += __shfl_xor_sync(0xffffffffu, ssum, o);
        if (lane == 0) redbuf[4 + warp] = ssum;
    }
    __syncthreads();
    const float inv = 1.f / (redbuf[4] + redbuf[5]);
    if (tid < 64) sc[tid] = p * inv;
    __syncthreads();
    float acc = 0.f;
    for (int j = 0; j < nn; j++)
        acc = fmaf(sc[j], g_v[(size_t)(s + j) * HDIM + tid], acc);
    out[(size_t)i * HDIM + tid] = acc;
}

// ---------------------------------------------------------------------------
extern "C" void kernel_launch(void* const* d_in, const int* in_sizes, int n_in,
                              void* d_out, int out_size)
{
    const float* enc    = (const float*)d_in[0];
    const float* social = (const float*)d_in[1];
    const int*   starts = (const int*)  d_in[2];
    const int*   ends   = (const int*)  d_in[3];
    const float* Wq     = (const float*)d_in[4];
    const float* bq     = (const float*)d_in[5];
    const float* Wk     = (const float*)d_in[6];
    const float* bk     = (const float*)d_in[7];
    const float* Wv     = (const float*)d_in[8];
    const float* bv     = (const float*)d_in[9];
    float* out = (float*)d_out;

    const int B = in_sizes[0] / HDIM;
    const int N = in_sizes[1] / HDIM;

    float* qbuf;
    __nv_bfloat16 *ahi, *alo, *kthi, *ktlo, *vthi, *vtlo;
    cudaGetSymbolAddress((void**)&qbuf, g_q);
    cudaGetSymbolAddress((void**)&ahi,  g_ahi);
    cudaGetSymbolAddress((void**)&alo,  g_alo);
    cudaGetSymbolAddress((void**)&kthi, g_wkt_hi);
    cudaGetSymbolAddress((void**)&ktlo, g_wkt_lo);
    cudaGetSymbolAddress((void**)&vthi, g_wvt_hi);
    cudaGetSymbolAddress((void**)&vtlo, g_wvt_lo);

    cudaFuncSetAttribute(kv_mma_kernel, cudaFuncAttributeMaxDynamicSharedMemorySize, SMEM_BYTES);

    const float inv_sqrt_d = 1.0f / sqrtf((float)HDIM);

    // 1. Split social_ht into bf16 hi/lo
    split_a_kernel<<<(N * HDIM) / (256 * 8), 256>>>(social, ahi, alo);
    // 2. Transpose+split Wk, Wv
    split_w_kernel<<<dim3(HDIM, 2), HDIM>>>(Wk, Wv, kthi, ktlo, vthi, vtlo);
    // 3. Q (scalar, independent)
    gemm_bias_relu<<<dim3(HDIM / 64, B / 64), 256>>>(enc, Wq, bq, qbuf, inv_sqrt_d);
    // 4. K and V via mma.sync bf16 3-split, cp.async pipelined, 16 warps
    kv_mma_kernel<<<dim3(HDIM / 128, N / 128, 2), 512, SMEM_BYTES>>>(bk, bv);
    // 5. Windowed attention
    attn_kernel<<<B, 256>>>(starts, ends, out);
}

// round 8
// speedup vs baseline: 1.0304x; 1.0304x over previous
#include <cuda_runtime.h>
#include <cuda_bf16.h>
#include <math.h>
#include <math_constants.h>
#include <cstdint>

#define HDIM 256
#define MAXB 1024
#define MAXN 32768

// ---------------------------------------------------------------------------
// Scratch (__device__ globals; no dynamic allocation allowed)
// ---------------------------------------------------------------------------
__device__ float g_q[(size_t)MAXB * HDIM];
__device__ float g_k[(size_t)MAXN * HDIM];
__device__ float g_v[(size_t)MAXN * HDIM];
__device__ __nv_bfloat16 g_wkt_hi[HDIM * HDIM];   // W^T splits: [n][k], k contiguous
__device__ __nv_bfloat16 g_wkt_lo[HDIM * HDIM];
__device__ __nv_bfloat16 g_wvt_hi[HDIM * HDIM];
__device__ __nv_bfloat16 g_wvt_lo[HDIM * HDIM];

// Transpose + split both weight matrices: out[n][k] = split(W[k][n])
__global__ void __launch_bounds__(256) split_w_kernel(
    const float* __restrict__ Wk, const float* __restrict__ Wv,
    __nv_bfloat16* __restrict__ khi, __nv_bfloat16* __restrict__ klo,
    __nv_bfloat16* __restrict__ vhi, __nv_bfloat16* __restrict__ vlo)
{
    const int n = blockIdx.x, k = threadIdx.x;
    const float* W = blockIdx.y ? Wv : Wk;
    __nv_bfloat16* oh = blockIdx.y ? vhi : khi;
    __nv_bfloat16* ol = blockIdx.y ? vlo : klo;
    float a = W[k * HDIM + n];
    __nv_bfloat16 h = __float2bfloat16(a);
    oh[n * HDIM + k] = h;
    ol[n * HDIM + k] = __float2bfloat16(a - __bfloat162float(h));
}

// ---------------------------------------------------------------------------
// K/V GEMM via mma.sync.m16n8k16.bf16, cp.async double buffered.
// A loaded as RAW FP32 (no pre-split pass); hi/lo bf16 split done per-fragment
// in registers. 256 threads, 8 warps = 4(m) x 2(n); warp tile 32x64.
// 3-MMA split: hi*hi + hi*lo + lo*hi.
// ---------------------------------------------------------------------------
#define KC 64                         // K-chunk
#define NCHUNK (HDIM / KC)            // 4
#define SROWF 68                      // fp32 A smem row stride (floats); 272 B
#define SROWB 72                      // bf16 B smem row stride (elems); 144 B
#define A_TILE_BYTES (128 * SROWF * 4)        // 34816
#define B_TILE_BYTES (128 * SROWB * 2)        // 18432
#define STAGE_BYTES (A_TILE_BYTES + 2 * B_TILE_BYTES)   // 71680
#define SMEM_BYTES (2 * STAGE_BYTES)                    // 143360

__device__ __forceinline__ uint32_t lds32(const __nv_bfloat16* p, int elem_off) {
    return *(const uint32_t*)(p + elem_off);
}
__device__ __forceinline__ void mma_bf16(float* d, const uint32_t* a, uint32_t b0, uint32_t b1) {
    asm volatile(
        "mma.sync.aligned.m16n8k16.row.col.f32.bf16.bf16.f32 "
        "{%0,%1,%2,%3}, {%4,%5,%6,%7}, {%8,%9}, {%0,%1,%2,%3};\n"
        : "+f"(d[0]), "+f"(d[1]), "+f"(d[2]), "+f"(d[3])
        : "r"(a[0]), "r"(a[1]), "r"(a[2]), "r"(a[3]), "r"(b0), "r"(b1));
}
__device__ __forceinline__ void cp_async16(uint32_t smem_dst, const void* gsrc) {
    asm volatile("cp.async.cg.shared.global [%0], [%1], 16;\n" :: "r"(smem_dst), "l"(gsrc));
}
// Split one float2 (k, k+1) into packed-bf16 hi and lo fragment registers.
__device__ __forceinline__ void split2(float2 f, uint32_t& hi, uint32_t& lo) {
    __nv_bfloat162 h = __floats2bfloat162_rn(f.x, f.y);
    hi = *reinterpret_cast<uint32_t*>(&h);
    float lx = f.x - __bfloat162float(__low2bfloat16(h));
    float ly = f.y - __bfloat162float(__high2bfloat16(h));
    __nv_bfloat162 l = __floats2bfloat162_rn(lx, ly);
    lo = *reinterpret_cast<uint32_t*>(&l);
}

__global__ void __launch_bounds__(256, 1) kv_mma_kernel(
    const float* __restrict__ gA,       // social_ht [N, 256] fp32
    const float* __restrict__ bk, const float* __restrict__ bv)
{
    extern __shared__ char smraw[];

    const int tid = threadIdx.x;
    const int wid = tid >> 5;
    const int lane = tid & 31;
    const int grp = lane >> 2;      // 0..7
    const int qid = lane & 3;       // 0..3
    const int warp_m = wid & 3;     // 4 warps along m (32 rows each)
    const int warp_n = wid >> 2;    // 2 warps along n (64 cols each)

    const int bn = blockIdx.x;      // n-tile (0..1)
    const int bm = blockIdx.y;      // m-tile (0..255)
    const int mat = blockIdx.z;     // 0 = K, 1 = V

    const __nv_bfloat16* gBhi = mat ? g_wvt_hi : g_wkt_hi;
    const __nv_bfloat16* gBlo = mat ? g_wvt_lo : g_wkt_lo;
    float* C = mat ? g_v : g_k;
    const float* bias = mat ? bv : bk;

    uint32_t smem_u32;
    {
        uint64_t t = __cvta_generic_to_shared(smraw);
        smem_u32 = (uint32_t)t;
    }

    auto prefetch = [&](int s, int c) {
        uint32_t stage = smem_u32 + s * STAGE_BYTES;
        // A: fp32, 128 rows x 64 floats = 128 x 16 segs of 16B -> 8 per thread
        const float* srcA = gA + (size_t)(bm * 128) * HDIM + c * KC;
        #pragma unroll
        for (int u = 0; u < 8; u++) {
            int seg = u * 256 + tid;
            int row = seg >> 4, cs = seg & 15;
            cp_async16(stage + row * (SROWF * 4) + cs * 16,
                       srcA + (size_t)row * HDIM + cs * 4);
        }
        // B hi/lo: bf16, 128 rows x 64 elems = 128 x 8 segs -> 4 per thread each
        const __nv_bfloat16* gB[2] = {gBhi, gBlo};
        #pragma unroll
        for (int arr = 0; arr < 2; arr++) {
            const __nv_bfloat16* src = gB[arr] + (size_t)(bn * 128) * HDIM + c * KC;
            uint32_t dstb = stage + A_TILE_BYTES + arr * B_TILE_BYTES;
            #pragma unroll
            for (int u = 0; u < 4; u++) {
                int seg = u * 256 + tid;
                int row = seg >> 3, cs = seg & 7;
                cp_async16(dstb + row * (SROWB * 2) + cs * 16,
                           src + (size_t)row * HDIM + cs * 8);
            }
        }
        asm volatile("cp.async.commit_group;\n");
    };

    float acc[2][8][4] = {};

    prefetch(0, 0);

    for (int c = 0; c < NCHUNK; c++) {
        if (c + 1 < NCHUNK) {
            prefetch((c + 1) & 1, c + 1);
            asm volatile("cp.async.wait_group 1;\n");
        } else {
            asm volatile("cp.async.wait_group 0;\n");
        }
        __syncthreads();

        const char* st = smraw + (c & 1) * STAGE_BYTES;
        const float* sA = (const float*)st;
        const __nv_bfloat16* sBhi = (const __nv_bfloat16*)(st + A_TILE_BYTES);
        const __nv_bfloat16* sBlo = (const __nv_bfloat16*)(st + A_TILE_BYTES + B_TILE_BYTES);

        #pragma unroll
        for (int ks = 0; ks < KC / 16; ks++) {
            const int k0 = ks * 16;
            uint32_t ahi[2][4], alo[2][4];
            #pragma unroll
            for (int mi = 0; mi < 2; mi++) {
                const float* a0 = sA + (warp_m * 32 + mi * 16 + grp) * SROWF + k0 + 2 * qid;
                float2 f00 = *(const float2*)(a0);              // row, k
                float2 f10 = *(const float2*)(a0 + 8 * SROWF);  // row+8, k
                float2 f01 = *(const float2*)(a0 + 8);          // row, k+8
                float2 f11 = *(const float2*)(a0 + 8 * SROWF + 8);
                split2(f00, ahi[mi][0], alo[mi][0]);
                split2(f10, ahi[mi][1], alo[mi][1]);
                split2(f01, ahi[mi][2], alo[mi][2]);
                split2(f11, ahi[mi][3], alo[mi][3]);
            }
            #pragma unroll
            for (int nb = 0; nb < 8; nb++) {
                const int bbase = (warp_n * 64 + nb * 8 + grp) * SROWB + k0 + 2 * qid;
                uint32_t bh0 = lds32(sBhi, bbase), bh1 = lds32(sBhi, bbase + 8);
                uint32_t bl0 = lds32(sBlo, bbase), bl1 = lds32(sBlo, bbase + 8);
                #pragma unroll
                for (int mi = 0; mi < 2; mi++) {
                    mma_bf16(acc[mi][nb], ahi[mi], bh0, bh1);
                    mma_bf16(acc[mi][nb], ahi[mi], bl0, bl1);
                    mma_bf16(acc[mi][nb], alo[mi], bh0, bh1);
                }
            }
        }
        __syncthreads();   // readers done before next iteration's prefetch overwrites
    }

    // Epilogue: bias + relu, fp32 stores.
    #pragma unroll
    for (int mi = 0; mi < 2; mi++) {
        const int row = bm * 128 + warp_m * 32 + mi * 16 + grp;
        #pragma unroll
        for (int nb = 0; nb < 8; nb++) {
            const int col = bn * 128 + warp_n * 64 + nb * 8 + 2 * qid;
            float2 bz = *(const float2*)(bias + col);
            float2 o0, o1;
            o0.x = fmaxf(acc[mi][nb][0] + bz.x, 0.f);
            o0.y = fmaxf(acc[mi][nb][1] + bz.y, 0.f);
            o1.x = fmaxf(acc[mi][nb][2] + bz.x, 0.f);
            o1.y = fmaxf(acc[mi][nb][3] + bz.y, 0.f);
            *(float2*)(C + (size_t)row * HDIM + col) = o0;
            *(float2*)(C + (size_t)(row + 8) * HDIM + col) = o1;
        }
    }
}

// ---------------------------------------------------------------------------
// Q GEMM (scalar, tiny: 1024x256x256) — unchanged, known-correct.
// ---------------------------------------------------------------------------
__global__ void __launch_bounds__(256) gemm_bias_relu(
    const float* __restrict__ A, const float* __restrict__ W,
    const float* __restrict__ bias, float* __restrict__ C, float scale)
{
    __shared__ float As[16][65];
    __shared__ float Ws[16][64];
    const int tid = threadIdx.x;
    const int bm = blockIdx.y * 64, bn = blockIdx.x * 64;
    const int tx = tid & 15, ty = tid >> 4;
    const int lm = tid >> 2, lk4 = (tid & 3) * 4;
    const int lwk = tid >> 4, lwn = (tid & 15) * 4;
    const float* Arow = A + (size_t)(bm + lm) * HDIM;
    float acc[4][4] = {};
    for (int k0 = 0; k0 < HDIM; k0 += 16) {
        float4 a4 = *(const float4*)(Arow + k0 + lk4);
        float4 w4 = *(const float4*)(W + (size_t)(k0 + lwk) * HDIM + bn + lwn);
        As[lk4 + 0][lm] = a4.x; As[lk4 + 1][lm] = a4.y;
        As[lk4 + 2][lm] = a4.z; As[lk4 + 3][lm] = a4.w;
        *(float4*)&Ws[lwk][lwn] = w4;
        __syncthreads();
        #pragma unroll
        for (int kk = 0; kk < 16; kk++) {
            float a[4], w[4];
            #pragma unroll
            for (int i = 0; i < 4; i++) a[i] = As[kk][ty * 4 + i];
            #pragma unroll
            for (int j = 0; j < 4; j++) w[j] = Ws[kk][tx * 4 + j];
            #pragma unroll
            for (int i = 0; i < 4; i++)
                #pragma unroll
                for (int j = 0; j < 4; j++)
                    acc[i][j] = fmaf(a[i], w[j], acc[i][j]);
        }
        __syncthreads();
    }
    const int col = bn + tx * 4;
    float c0 = bias[col], c1 = bias[col + 1], c2 = bias[col + 2], c3 = bias[col + 3];
    #pragma unroll
    for (int i = 0; i < 4; i++) {
        const int row = bm + ty * 4 + i;
        float4 r;
        r.x = fmaxf(acc[i][0] + c0, 0.f) * scale;
        r.y = fmaxf(acc[i][1] + c1, 0.f) * scale;
        r.z = fmaxf(acc[i][2] + c2, 0.f) * scale;
        r.w = fmaxf(acc[i][3] + c3, 0.f) * scale;
        *(float4*)(C + (size_t)row * HDIM + col) = r;
    }
}

// ---------------------------------------------------------------------------
// Windowed attention — unchanged, known-correct.
// ---------------------------------------------------------------------------
__global__ void __launch_bounds__(256) attn_kernel(
    const int* __restrict__ starts, const int* __restrict__ ends, float* __restrict__ out)
{
    const int i = blockIdx.x;
    const int tid = threadIdx.x;
    const int warp = tid >> 5, lane = tid & 31;
    __shared__ float qs[HDIM];
    __shared__ float sc[64];
    __shared__ float redbuf[8];
    qs[tid] = g_q[(size_t)i * HDIM + tid];
    const int s = starts[i];
    const int nn = ends[i] - s;
    __syncthreads();
    for (int j = warp; j < nn; j += 8) {
        const float* krow = g_k + (size_t)(s + j) * HDIM;
        float acc = 0.f;
        #pragma unroll
        for (int c = 0; c < HDIM / 32; c++)
            acc = fmaf(qs[lane + 32 * c], krow[lane + 32 * c], acc);
        #pragma unroll
        for (int o = 16; o; o >>= 1) acc += __shfl_xor_sync(0xffffffffu, acc, o);
        if (lane == 0) sc[j] = acc;
    }
    __syncthreads();
    float x = -CUDART_INF_F;
    if (tid < 64) {
        x = (tid < nn) ? sc[tid] : -CUDART_INF_F;
        float m = x;
        #pragma unroll
        for (int o = 16; o; o >>= 1) m = fmaxf(m, __shfl_xor_sync(0xffffffffu, m, o));
        if (lane == 0) redbuf[warp] = m;
    }
    __syncthreads();
    const float m = fmaxf(redbuf[0], redbuf[1]);
    float p = 0.f;
    if (tid < 64) {
        p = (tid < nn) ? expf(x - m) : 0.f;
        float ssum = p;
        #pragma unroll
        for (int o = 16; o; o >>= 1) ssum += __shfl_xor_sync(0xffffffffu, ssum, o);
        if (lane == 0) redbuf[4 + warp] = ssum;
    }
    __syncthreads();
    const float inv = 1.f / (redbuf[4] + redbuf[5]);
    if (tid < 64) sc[tid] = p * inv;
    __syncthreads();
    float acc = 0.f;
    for (int j = 0; j < nn; j++)
        acc = fmaf(sc[j], g_v[(size_t)(s + j) * HDIM + tid], acc);
    out[(size_t)i * HDIM + tid] = acc;
}

// ---------------------------------------------------------------------------
extern "C" void kernel_launch(void* const* d_in, const int* in_sizes, int n_in,
                              void* d_out, int out_size)
{
    const float* enc    = (const float*)d_in[0];
    const float* social = (const float*)d_in[1];
    const int*   starts = (const int*)  d_in[2];
    const int*   ends   = (const int*)  d_in[3];
    const float* Wq     = (const float*)d_in[4];
    const float* bq     = (const float*)d_in[5];
    const float* Wk     = (const float*)d_in[6];
    const float* bk     = (const float*)d_in[7];
    const float* Wv     = (const float*)d_in[8];
    const float* bv     = (const float*)d_in[9];
    float* out = (float*)d_out;

    const int B = in_sizes[0] / HDIM;
    const int N = in_sizes[1] / HDIM;

    float* qbuf;
    __nv_bfloat16 *kthi, *ktlo, *vthi, *vtlo;
    cudaGetSymbolAddress((void**)&qbuf, g_q);
    cudaGetSymbolAddress((void**)&kthi, g_wkt_hi);
    cudaGetSymbolAddress((void**)&ktlo, g_wkt_lo);
    cudaGetSymbolAddress((void**)&vthi, g_wvt_hi);
    cudaGetSymbolAddress((void**)&vtlo, g_wvt_lo);

    cudaFuncSetAttribute(kv_mma_kernel, cudaFuncAttributeMaxDynamicSharedMemorySize, SMEM_BYTES);

    const float inv_sqrt_d = 1.0f / sqrtf((float)HDIM);

    // 1. Transpose+split Wk, Wv (tiny)
    split_w_kernel<<<dim3(HDIM, 2), HDIM>>>(Wk, Wv, kthi, ktlo, vthi, vtlo);
    // 2. Q (scalar, independent)
    gemm_bias_relu<<<dim3(HDIM / 64, B / 64), 256>>>(enc, Wq, bq, qbuf, inv_sqrt_d);
    // 3. K and V via mma.sync bf16 3-split; A split fused in-kernel
    kv_mma_kernel<<<dim3(HDIM / 128, N / 128, 2), 256, SMEM_BYTES>>>(social, bk, bv);
    // 4. Windowed attention
    attn_kernel<<<B, 256>>>(starts, ends, out);
}

// round 9
// speedup vs baseline: 1.0732x; 1.0415x over previous
#include <cuda_runtime.h>
#include <cuda_bf16.h>
#include <math.h>
#include <math_constants.h>
#include <cstdint>

#define HDIM 256
#define MAXB 1024
#define MAXN 32768

// ---------------------------------------------------------------------------
// Scratch (__device__ globals; no dynamic allocation allowed)
// ---------------------------------------------------------------------------
__device__ float g_q[(size_t)MAXB * HDIM];
__device__ float g_k[(size_t)MAXN * HDIM];
__device__ float g_v[(size_t)MAXN * HDIM];
__device__ __nv_bfloat16 g_wkt_hi[HDIM * HDIM];   // W^T splits: [n][k], k contiguous
__device__ __nv_bfloat16 g_wkt_lo[HDIM * HDIM];
__device__ __nv_bfloat16 g_wvt_hi[HDIM * HDIM];
__device__ __nv_bfloat16 g_wvt_lo[HDIM * HDIM];
__device__ __nv_bfloat16 g_wqt_hi[HDIM * HDIM];
__device__ __nv_bfloat16 g_wqt_lo[HDIM * HDIM];

// Transpose + split the three weight matrices: out[n][k] = split(W[k][n])
__global__ void __launch_bounds__(256) split_w_kernel(
    const float* __restrict__ Wk, const float* __restrict__ Wv, const float* __restrict__ Wq,
    __nv_bfloat16* __restrict__ khi, __nv_bfloat16* __restrict__ klo,
    __nv_bfloat16* __restrict__ vhi, __nv_bfloat16* __restrict__ vlo,
    __nv_bfloat16* __restrict__ qhi, __nv_bfloat16* __restrict__ qlo)
{
    const int n = blockIdx.x, k = threadIdx.x;
    const float* W = (blockIdx.y == 0) ? Wk : (blockIdx.y == 1 ? Wv : Wq);
    __nv_bfloat16* oh = (blockIdx.y == 0) ? khi : (blockIdx.y == 1 ? vhi : qhi);
    __nv_bfloat16* ol = (blockIdx.y == 0) ? klo : (blockIdx.y == 1 ? vlo : qlo);
    float a = W[k * HDIM + n];
    __nv_bfloat16 h = __float2bfloat16(a);
    oh[n * HDIM + k] = h;
    ol[n * HDIM + k] = __float2bfloat16(a - __bfloat162float(h));
}

// ---------------------------------------------------------------------------
// Shared GEMM tile body: C[128,128] tile = relu(A_fp32 @ Wsplit^T + bias)*scale
// mma.sync.m16n8k16.bf16, cp.async double buffered, in-register A hi/lo split.
// 256 threads, 8 warps = 4(m) x 2(n); warp tile 32x64.
// ---------------------------------------------------------------------------
#define KC 64                         // K-chunk
#define NCHUNK (HDIM / KC)            // 4
#define SROWF 68                      // fp32 A smem row stride (floats); 272 B
#define SROWB 72                      // bf16 B smem row stride (elems); 144 B
#define A_TILE_BYTES (128 * SROWF * 4)        // 34816
#define B_TILE_BYTES (128 * SROWB * 2)        // 18432
#define STAGE_BYTES (A_TILE_BYTES + 2 * B_TILE_BYTES)   // 71680
#define SMEM_BYTES (2 * STAGE_BYTES)                    // 143360

__device__ __forceinline__ uint32_t lds32(const __nv_bfloat16* p, int elem_off) {
    return *(const uint32_t*)(p + elem_off);
}
__device__ __forceinline__ void mma_bf16(float* d, const uint32_t* a, uint32_t b0, uint32_t b1) {
    asm volatile(
        "mma.sync.aligned.m16n8k16.row.col.f32.bf16.bf16.f32 "
        "{%0,%1,%2,%3}, {%4,%5,%6,%7}, {%8,%9}, {%0,%1,%2,%3};\n"
        : "+f"(d[0]), "+f"(d[1]), "+f"(d[2]), "+f"(d[3])
        : "r"(a[0]), "r"(a[1]), "r"(a[2]), "r"(a[3]), "r"(b0), "r"(b1));
}
__device__ __forceinline__ void cp_async16(uint32_t smem_dst, const void* gsrc) {
    asm volatile("cp.async.cg.shared.global [%0], [%1], 16;\n" :: "r"(smem_dst), "l"(gsrc));
}
// Split one float2 (k, k+1) into packed-bf16 hi and lo fragment registers.
__device__ __forceinline__ void split2(float2 f, uint32_t& hi, uint32_t& lo) {
    __nv_bfloat162 h = __floats2bfloat162_rn(f.x, f.y);
    hi = *reinterpret_cast<uint32_t*>(&h);
    float lx = f.x - __bfloat162float(__low2bfloat16(h));
    float ly = f.y - __bfloat162float(__high2bfloat16(h));
    __nv_bfloat162 l = __floats2bfloat162_rn(lx, ly);
    lo = *reinterpret_cast<uint32_t*>(&l);
}

__device__ __forceinline__ void gemm_tile_body(
    const float* __restrict__ gA,
    const __nv_bfloat16* __restrict__ gBhi, const __nv_bfloat16* __restrict__ gBlo,
    const float* __restrict__ bias, float* __restrict__ C, float scale,
    int bm, int bn, char* smraw)
{
    const int tid = threadIdx.x;
    const int wid = tid >> 5;
    const int lane = tid & 31;
    const int grp = lane >> 2;      // 0..7
    const int qid = lane & 3;       // 0..3
    const int warp_m = wid & 3;     // 4 warps along m (32 rows each)
    const int warp_n = wid >> 2;    // 2 warps along n (64 cols each)

    uint32_t smem_u32;
    {
        uint64_t t = __cvta_generic_to_shared(smraw);
        smem_u32 = (uint32_t)t;
    }

    auto prefetch = [&](int s, int c) {
        uint32_t stage = smem_u32 + s * STAGE_BYTES;
        // A: fp32, 128 rows x 64 floats = 128 x 16 segs of 16B -> 8 per thread
        const float* srcA = gA + (size_t)(bm * 128) * HDIM + c * KC;
        #pragma unroll
        for (int u = 0; u < 8; u++) {
            int seg = u * 256 + tid;
            int row = seg >> 4, cs = seg & 15;
            cp_async16(stage + row * (SROWF * 4) + cs * 16,
                       srcA + (size_t)row * HDIM + cs * 4);
        }
        // B hi/lo: bf16, 128 rows x 64 elems = 128 x 8 segs -> 4 per thread each
        const __nv_bfloat16* gB[2] = {gBhi, gBlo};
        #pragma unroll
        for (int arr = 0; arr < 2; arr++) {
            const __nv_bfloat16* src = gB[arr] + (size_t)(bn * 128) * HDIM + c * KC;
            uint32_t dstb = stage + A_TILE_BYTES + arr * B_TILE_BYTES;
            #pragma unroll
            for (int u = 0; u < 4; u++) {
                int seg = u * 256 + tid;
                int row = seg >> 3, cs = seg & 7;
                cp_async16(dstb + row * (SROWB * 2) + cs * 16,
                           src + (size_t)row * HDIM + cs * 8);
            }
        }
        asm volatile("cp.async.commit_group;\n");
    };

    float acc[2][8][4] = {};

    prefetch(0, 0);

    for (int c = 0; c < NCHUNK; c++) {
        if (c + 1 < NCHUNK) {
            prefetch((c + 1) & 1, c + 1);
            asm volatile("cp.async.wait_group 1;\n");
        } else {
            asm volatile("cp.async.wait_group 0;\n");
        }
        __syncthreads();

        const char* st = smraw + (c & 1) * STAGE_BYTES;
        const float* sA = (const float*)st;
        const __nv_bfloat16* sBhi = (const __nv_bfloat16*)(st + A_TILE_BYTES);
        const __nv_bfloat16* sBlo = (const __nv_bfloat16*)(st + A_TILE_BYTES + B_TILE_BYTES);

        #pragma unroll
        for (int ks = 0; ks < KC / 16; ks++) {
            const int k0 = ks * 16;
            uint32_t ahi[2][4], alo[2][4];
            #pragma unroll
            for (int mi = 0; mi < 2; mi++) {
                const float* a0 = sA + (warp_m * 32 + mi * 16 + grp) * SROWF + k0 + 2 * qid;
                float2 f00 = *(const float2*)(a0);              // row, k
                float2 f10 = *(const float2*)(a0 + 8 * SROWF);  // row+8, k
                float2 f01 = *(const float2*)(a0 + 8);          // row, k+8
                float2 f11 = *(const float2*)(a0 + 8 * SROWF + 8);
                split2(f00, ahi[mi][0], alo[mi][0]);
                split2(f10, ahi[mi][1], alo[mi][1]);
                split2(f01, ahi[mi][2], alo[mi][2]);
                split2(f11, ahi[mi][3], alo[mi][3]);
            }
            #pragma unroll
            for (int nb = 0; nb < 8; nb++) {
                const int bbase = (warp_n * 64 + nb * 8 + grp) * SROWB + k0 + 2 * qid;
                uint32_t bh0 = lds32(sBhi, bbase), bh1 = lds32(sBhi, bbase + 8);
                uint32_t bl0 = lds32(sBlo, bbase), bl1 = lds32(sBlo, bbase + 8);
                #pragma unroll
                for (int mi = 0; mi < 2; mi++) {
                    mma_bf16(acc[mi][nb], ahi[mi], bh0, bh1);
                    mma_bf16(acc[mi][nb], ahi[mi], bl0, bl1);
                    mma_bf16(acc[mi][nb], alo[mi], bh0, bh1);
                }
            }
        }
        __syncthreads();   // readers done before next iteration's prefetch overwrites
    }

    // Epilogue: bias + relu (+ post-relu scale), fp32 stores.
    #pragma unroll
    for (int mi = 0; mi < 2; mi++) {
        const int row = bm * 128 + warp_m * 32 + mi * 16 + grp;
        #pragma unroll
        for (int nb = 0; nb < 8; nb++) {
            const int col = bn * 128 + warp_n * 64 + nb * 8 + 2 * qid;
            float2 bz = *(const float2*)(bias + col);
            float2 o0, o1;
            o0.x = fmaxf(acc[mi][nb][0] + bz.x, 0.f) * scale;
            o0.y = fmaxf(acc[mi][nb][1] + bz.y, 0.f) * scale;
            o1.x = fmaxf(acc[mi][nb][2] + bz.x, 0.f) * scale;
            o1.y = fmaxf(acc[mi][nb][3] + bz.y, 0.f) * scale;
            *(float2*)(C + (size_t)row * HDIM + col) = o0;
            *(float2*)(C + (size_t)(row + 8) * HDIM + col) = o1;
        }
    }
}

// K/V wrapper: grid (2 n-tiles, 256 m-tiles, 2 mats)
__global__ void __launch_bounds__(256, 1) kv_mma_kernel(
    const float* __restrict__ gA,
    const float* __restrict__ bk, const float* __restrict__ bv)
{
    extern __shared__ char smraw[];
    const int mat = blockIdx.z;
    gemm_tile_body(gA,
                   mat ? g_wvt_hi : g_wkt_hi, mat ? g_wvt_lo : g_wkt_lo,
                   mat ? bv : bk, mat ? g_v : g_k, 1.0f,
                   blockIdx.y, blockIdx.x, smraw);
}

// Q wrapper: grid (2 n-tiles, 8 m-tiles); post-ReLU scale = 1/sqrt(d)
__global__ void __launch_bounds__(256, 1) q_mma_kernel(
    const float* __restrict__ gA, const float* __restrict__ bq, float scale)
{
    extern __shared__ char smraw[];
    gemm_tile_body(gA, g_wqt_hi, g_wqt_lo, bq, g_q, scale,
                   blockIdx.y, blockIdx.x, smraw);
}

// ---------------------------------------------------------------------------
// Windowed attention — unchanged, known-correct.
// ---------------------------------------------------------------------------
__global__ void __launch_bounds__(256) attn_kernel(
    const int* __restrict__ starts, const int* __restrict__ ends, float* __restrict__ out)
{
    const int i = blockIdx.x;
    const int tid = threadIdx.x;
    const int warp = tid >> 5, lane = tid & 31;
    __shared__ float qs[HDIM];
    __shared__ float sc[64];
    __shared__ float redbuf[8];
    qs[tid] = g_q[(size_t)i * HDIM + tid];
    const int s = starts[i];
    const int nn = ends[i] - s;
    __syncthreads();
    for (int j = warp; j < nn; j += 8) {
        const float* krow = g_k + (size_t)(s + j) * HDIM;
        float acc = 0.f;
        #pragma unroll
        for (int c = 0; c < HDIM / 32; c++)
            acc = fmaf(qs[lane + 32 * c], krow[lane + 32 * c], acc);
        #pragma unroll
        for (int o = 16; o; o >>= 1) acc += __shfl_xor_sync(0xffffffffu, acc, o);
        if (lane == 0) sc[j] = acc;
    }
    __syncthreads();
    float x = -CUDART_INF_F;
    if (tid < 64) {
        x = (tid < nn) ? sc[tid] : -CUDART_INF_F;
        float m = x;
        #pragma unroll
        for (int o = 16; o; o >>= 1) m = fmaxf(m, __shfl_xor_sync(0xffffffffu, m, o));
        if (lane == 0) redbuf[warp] = m;
    }
    __syncthreads();
    const float m = fmaxf(redbuf[0], redbuf[1]);
    float p = 0.f;
    if (tid < 64) {
        p = (tid < nn) ? expf(x - m) : 0.f;
        float ssum = p;
        #pragma unroll
        for (int o = 16; o; o >>= 1) ssum += __shfl_xor_sync(0xffffffffu, ssum, o);
        if (lane == 0) redbuf[4 + warp] = ssum;
    }
    __syncthreads();
    const float inv = 1.f / (redbuf[4] + redbuf[5]);
    if (tid < 64) sc[tid] = p * inv;
    __syncthreads();
    float acc = 0.f;
    for (int j = 0; j < nn; j++)
        acc = fmaf(sc[j], g_v[(size_t)(s + j) * HDIM + tid], acc);
    out[(size_t)i * HDIM + tid] = acc;
}

// ---------------------------------------------------------------------------
extern "C" void kernel_launch(void* const* d_in, const int* in_sizes, int n_in,
                              void* d_out, int out_size)
{
    const float* enc    = (const float*)d_in[0];
    const float* social = (const float*)d_in[1];
    const int*   starts = (const int*)  d_in[2];
    const int*   ends   = (const int*)  d_in[3];
    const float* Wq     = (const float*)d_in[4];
    const float* bq     = (const float*)d_in[5];
    const float* Wk     = (const float*)d_in[6];
    const float* bk     = (const float*)d_in[7];
    const float* Wv     = (const float*)d_in[8];
    const float* bv     = (const float*)d_in[9];
    float* out = (float*)d_out;

    const int B = in_sizes[0] / HDIM;
    const int N = in_sizes[1] / HDIM;

    __nv_bfloat16 *kthi, *ktlo, *vthi, *vtlo, *qthi, *qtlo;
    cudaGetSymbolAddress((void**)&kthi, g_wkt_hi);
    cudaGetSymbolAddress((void**)&ktlo, g_wkt_lo);
    cudaGetSymbolAddress((void**)&vthi, g_wvt_hi);
    cudaGetSymbolAddress((void**)&vtlo, g_wvt_lo);
    cudaGetSymbolAddress((void**)&qthi, g_wqt_hi);
    cudaGetSymbolAddress((void**)&qtlo, g_wqt_lo);

    cudaFuncSetAttribute(kv_mma_kernel, cudaFuncAttributeMaxDynamicSharedMemorySize, SMEM_BYTES);
    cudaFuncSetAttribute(q_mma_kernel,  cudaFuncAttributeMaxDynamicSharedMemorySize, SMEM_BYTES);

    const float inv_sqrt_d = 1.0f / sqrtf((float)HDIM);

    // 1. Transpose+split Wk, Wv, Wq (tiny)
    split_w_kernel<<<dim3(HDIM, 3), HDIM>>>(Wk, Wv, Wq, kthi, ktlo, vthi, vtlo, qthi, qtlo);
    // 2. K and V via mma.sync bf16 3-split; A split fused in-kernel
    kv_mma_kernel<<<dim3(HDIM / 128, N / 128, 2), 256, SMEM_BYTES>>>(social, bk, bv);
    // 3. Q via same mma path (16 CTAs)
    q_mma_kernel<<<dim3(HDIM / 128, B / 128), 256, SMEM_BYTES>>>(enc, bq, inv_sqrt_d);
    // 4. Windowed attention
    attn_kernel<<<B, 256>>>(starts, ends, out);
}

// round 11
// speedup vs baseline: 1.2038x; 1.1217x over previous
#include <cuda_runtime.h>
#include <cuda_bf16.h>
#include <math.h>
#include <math_constants.h>
#include <cstdint>

#define HDIM 256
#define MAXB 1024
#define MAXN 32768

// ---------------------------------------------------------------------------
// Scratch (__device__ globals; no dynamic allocation allowed)
// ---------------------------------------------------------------------------
__device__ float g_q[(size_t)MAXB * HDIM];
__device__ float g_k[(size_t)MAXN * HDIM];
__device__ float g_v[(size_t)MAXN * HDIM];
__device__ __nv_bfloat16 g_wkt_hi[HDIM * HDIM];   // W^T splits: [n][k], k contiguous
__device__ __nv_bfloat16 g_wkt_lo[HDIM * HDIM];
__device__ __nv_bfloat16 g_wvt_hi[HDIM * HDIM];
__device__ __nv_bfloat16 g_wvt_lo[HDIM * HDIM];
__device__ __nv_bfloat16 g_wqt_hi[HDIM * HDIM];
__device__ __nv_bfloat16 g_wqt_lo[HDIM * HDIM];

// Transpose + split the three weight matrices: out[n][k] = split(W[k][n])
__global__ void __launch_bounds__(256) split_w_kernel(
    const float* __restrict__ Wk, const float* __restrict__ Wv, const float* __restrict__ Wq,
    __nv_bfloat16* __restrict__ khi, __nv_bfloat16* __restrict__ klo,
    __nv_bfloat16* __restrict__ vhi, __nv_bfloat16* __restrict__ vlo,
    __nv_bfloat16* __restrict__ qhi, __nv_bfloat16* __restrict__ qlo)
{
    const int n = blockIdx.x, k = threadIdx.x;
    const float* W = (blockIdx.y == 0) ? Wk : (blockIdx.y == 1 ? Wv : Wq);
    __nv_bfloat16* oh = (blockIdx.y == 0) ? khi : (blockIdx.y == 1 ? vhi : qhi);
    __nv_bfloat16* ol = (blockIdx.y == 0) ? klo : (blockIdx.y == 1 ? vlo : qlo);
    float a = W[k * HDIM + n];
    __nv_bfloat16 h = __float2bfloat16(a);
    oh[n * HDIM + k] = h;
    ol[n * HDIM + k] = __float2bfloat16(a - __bfloat162float(h));
}

// ---------------------------------------------------------------------------
// Shared GEMM tile body: C[128,128] tile = relu(A_fp32 @ Wsplit^T + bias)*scale
// mma.sync.m16n8k16.bf16, cp.async double buffered, in-register A hi/lo split.
// 256 threads, 8 warps = 4(m) x 2(n); warp tile 32x64.
// ---------------------------------------------------------------------------
#define KC 64                         // K-chunk
#define NCHUNK (HDIM / KC)            // 4
#define SROWF 68                      // fp32 A smem row stride (floats); 272 B
#define SROWB 72                      // bf16 B smem row stride (elems); 144 B
#define A_TILE_BYTES (128 * SROWF * 4)        // 34816
#define B_TILE_BYTES (128 * SROWB * 2)        // 18432
#define STAGE_BYTES (A_TILE_BYTES + 2 * B_TILE_BYTES)   // 71680
#define SMEM_BYTES (2 * STAGE_BYTES)                    // 143360

__device__ __forceinline__ uint32_t lds32(const __nv_bfloat16* p, int elem_off) {
    return *(const uint32_t*)(p + elem_off);
}
__device__ __forceinline__ void mma_bf16(float* d, const uint32_t* a, uint32_t b0, uint32_t b1) {
    asm volatile(
        "mma.sync.aligned.m16n8k16.row.col.f32.bf16.bf16.f32 "
        "{%0,%1,%2,%3}, {%4,%5,%6,%7}, {%8,%9}, {%0,%1,%2,%3};\n"
        : "+f"(d[0]), "+f"(d[1]), "+f"(d[2]), "+f"(d[3])
        : "r"(a[0]), "r"(a[1]), "r"(a[2]), "r"(a[3]), "r"(b0), "r"(b1));
}
__device__ __forceinline__ void cp_async16(uint32_t smem_dst, const void* gsrc) {
    asm volatile("cp.async.cg.shared.global [%0], [%1], 16;\n" :: "r"(smem_dst), "l"(gsrc));
}
// Split one float2 (k, k+1) into packed-bf16 hi and lo fragment registers.
__device__ __forceinline__ void split2(float2 f, uint32_t& hi, uint32_t& lo) {
    __nv_bfloat162 h = __floats2bfloat162_rn(f.x, f.y);
    hi = *reinterpret_cast<uint32_t*>(&h);
    float lx = f.x - __bfloat162float(__low2bfloat16(h));
    float ly = f.y - __bfloat162float(__high2bfloat16(h));
    __nv_bfloat162 l = __floats2bfloat162_rn(lx, ly);
    lo = *reinterpret_cast<uint32_t*>(&l);
}

__device__ __forceinline__ void gemm_tile_body(
    const float* __restrict__ gA,
    const __nv_bfloat16* __restrict__ gBhi, const __nv_bfloat16* __restrict__ gBlo,
    const float* __restrict__ bias, float* __restrict__ C, float scale,
    int bm, int bn, char* smraw)
{
    const int tid = threadIdx.x;
    const int wid = tid >> 5;
    const int lane = tid & 31;
    const int grp = lane >> 2;      // 0..7
    const int qid = lane & 3;       // 0..3
    const int warp_m = wid & 3;     // 4 warps along m (32 rows each)
    const int warp_n = wid >> 2;    // 2 warps along n (64 cols each)

    uint32_t smem_u32;
    {
        uint64_t t = __cvta_generic_to_shared(smraw);
        smem_u32 = (uint32_t)t;
    }

    auto prefetch = [&](int s, int c) {
        uint32_t stage = smem_u32 + s * STAGE_BYTES;
        // A: fp32, 128 rows x 64 floats = 128 x 16 segs of 16B -> 8 per thread
        const float* srcA = gA + (size_t)(bm * 128) * HDIM + c * KC;
        #pragma unroll
        for (int u = 0; u < 8; u++) {
            int seg = u * 256 + tid;
            int row = seg >> 4, cs = seg & 15;
            cp_async16(stage + row * (SROWF * 4) + cs * 16,
                       srcA + (size_t)row * HDIM + cs * 4);
        }
        // B hi/lo: bf16, 128 rows x 64 elems = 128 x 8 segs -> 4 per thread each
        const __nv_bfloat16* gB[2] = {gBhi, gBlo};
        #pragma unroll
        for (int arr = 0; arr < 2; arr++) {
            const __nv_bfloat16* src = gB[arr] + (size_t)(bn * 128) * HDIM + c * KC;
            uint32_t dstb = stage + A_TILE_BYTES + arr * B_TILE_BYTES;
            #pragma unroll
            for (int u = 0; u < 4; u++) {
                int seg = u * 256 + tid;
                int row = seg >> 3, cs = seg & 7;
                cp_async16(dstb + row * (SROWB * 2) + cs * 16,
                           src + (size_t)row * HDIM + cs * 8);
            }
        }
        asm volatile("cp.async.commit_group;\n");
    };

    float acc[2][8][4] = {};

    prefetch(0, 0);

    for (int c = 0; c < NCHUNK; c++) {
        if (c + 1 < NCHUNK) {
            prefetch((c + 1) & 1, c + 1);
            asm volatile("cp.async.wait_group 1;\n");
        } else {
            asm volatile("cp.async.wait_group 0;\n");
        }
        __syncthreads();

        const char* st = smraw + (c & 1) * STAGE_BYTES;
        const float* sA = (const float*)st;
        const __nv_bfloat16* sBhi = (const __nv_bfloat16*)(st + A_TILE_BYTES);
        const __nv_bfloat16* sBlo = (const __nv_bfloat16*)(st + A_TILE_BYTES + B_TILE_BYTES);

        #pragma unroll
        for (int ks = 0; ks < KC / 16; ks++) {
            const int k0 = ks * 16;
            uint32_t ahi[2][4], alo[2][4];
            #pragma unroll
            for (int mi = 0; mi < 2; mi++) {
                const float* a0 = sA + (warp_m * 32 + mi * 16 + grp) * SROWF + k0 + 2 * qid;
                float2 f00 = *(const float2*)(a0);              // row, k
                float2 f10 = *(const float2*)(a0 + 8 * SROWF);  // row+8, k
                float2 f01 = *(const float2*)(a0 + 8);          // row, k+8
                float2 f11 = *(const float2*)(a0 + 8 * SROWF + 8);
                split2(f00, ahi[mi][0], alo[mi][0]);
                split2(f10, ahi[mi][1], alo[mi][1]);
                split2(f01, ahi[mi][2], alo[mi][2]);
                split2(f11, ahi[mi][3], alo[mi][3]);
            }
            #pragma unroll
            for (int nb = 0; nb < 8; nb++) {
                const int bbase = (warp_n * 64 + nb * 8 + grp) * SROWB + k0 + 2 * qid;
                uint32_t bh0 = lds32(sBhi, bbase), bh1 = lds32(sBhi, bbase + 8);
                uint32_t bl0 = lds32(sBlo, bbase), bl1 = lds32(sBlo, bbase + 8);
                #pragma unroll
                for (int mi = 0; mi < 2; mi++) {
                    mma_bf16(acc[mi][nb], ahi[mi], bh0, bh1);
                    mma_bf16(acc[mi][nb], ahi[mi], bl0, bl1);
                    mma_bf16(acc[mi][nb], alo[mi], bh0, bh1);
                }
            }
        }
        __syncthreads();   // readers done before next iteration's prefetch overwrites
    }

    // Epilogue: bias + relu (+ post-relu scale), fp32 stores.
    #pragma unroll
    for (int mi = 0; mi < 2; mi++) {
        const int row = bm * 128 + warp_m * 32 + mi * 16 + grp;
        #pragma unroll
        for (int nb = 0; nb < 8; nb++) {
            const int col = bn * 128 + warp_n * 64 + nb * 8 + 2 * qid;
            float2 bz = *(const float2*)(bias + col);
            float2 o0, o1;
            o0.x = fmaxf(acc[mi][nb][0] + bz.x, 0.f) * scale;
            o0.y = fmaxf(acc[mi][nb][1] + bz.y, 0.f) * scale;
            o1.x = fmaxf(acc[mi][nb][2] + bz.x, 0.f) * scale;
            o1.y = fmaxf(acc[mi][nb][3] + bz.y, 0.f) * scale;
            *(float2*)(C + (size_t)row * HDIM + col) = o0;
            *(float2*)(C + (size_t)(row + 8) * HDIM + col) = o1;
        }
    }
}

// K/V wrapper: grid (2 n-tiles, 256 m-tiles, 2 mats)
__global__ void __launch_bounds__(256, 1) kv_mma_kernel(
    const float* __restrict__ gA,
    const float* __restrict__ bk, const float* __restrict__ bv)
{
    extern __shared__ char smraw[];
    const int mat = blockIdx.z;
    gemm_tile_body(gA,
                   mat ? g_wvt_hi : g_wkt_hi, mat ? g_wvt_lo : g_wkt_lo,
                   mat ? bv : bk, mat ? g_v : g_k, 1.0f,
                   blockIdx.y, blockIdx.x, smraw);
}

// Q wrapper: grid (2 n-tiles, 8 m-tiles); post-ReLU scale = 1/sqrt(d)
__global__ void __launch_bounds__(256, 1) q_mma_kernel(
    const float* __restrict__ gA, const float* __restrict__ bq, float scale)
{
    extern __shared__ char smraw[];
    gemm_tile_body(gA, g_wqt_hi, g_wqt_lo, bq, g_q, scale,
                   blockIdx.y, blockIdx.x, smraw);
}

// ---------------------------------------------------------------------------
// Windowed attention, MLP-optimized.
// Score phase: 2x LDG.128 per K row. V phase: unroll x8, clamped rows,
// zero-padded weights (nn <= 63 guaranteed by problem: lens in [1,64)).
// ---------------------------------------------------------------------------
__global__ void __launch_bounds__(256) attn_kernel(
    const int* __restrict__ starts, const int* __restrict__ ends, float* __restrict__ out)
{
    const int i = blockIdx.x;
    const int tid = threadIdx.x;
    const int warp = tid >> 5, lane = tid & 31;
    __shared__ float qs[HDIM];
    __shared__ float sc[72];     // scores; entries >= nn stay 0
    __shared__ float redbuf[8];

    qs[tid] = g_q[(size_t)i * HDIM + tid];
    if (tid < 72) sc[tid] = 0.f;
    const int s = starts[i];
    const int nn = ends[i] - s;   // 1..63
    __syncthreads();

    // Scores: warp w handles neighbors w, w+8, ... Lane owns 8 contiguous floats.
    for (int j = warp; j < nn; j += 8) {
        const float4* krow = (const float4*)(g_k + (size_t)(s + j) * HDIM) + lane * 2;
        float4 k0 = krow[0], k1 = krow[1];
        const float4* qrow = (const float4*)qs + lane * 2;
        float4 q0 = qrow[0], q1 = qrow[1];
        float acc = k0.x * q0.x;
        acc = fmaf(k0.y, q0.y, acc);
        acc = fmaf(k0.z, q0.z, acc);
        acc = fmaf(k0.w, q0.w, acc);
        acc = fmaf(k1.x, q1.x, acc);
        acc = fmaf(k1.y, q1.y, acc);
        acc = fmaf(k1.z, q1.z, acc);
        acc = fmaf(k1.w, q1.w, acc);
        #pragma unroll
        for (int o = 16; o; o >>= 1) acc += __shfl_xor_sync(0xffffffffu, acc, o);
        if (lane == 0) sc[j] = acc;
    }
    __syncthreads();

    // Softmax over sc[0..nn) — threads 0..63 (2 warps).
    float x = -CUDART_INF_F;
    if (tid < 64) {
        x = (tid < nn) ? sc[tid] : -CUDART_INF_F;
        float m = x;
        #pragma unroll
        for (int o = 16; o; o >>= 1) m = fmaxf(m, __shfl_xor_sync(0xffffffffu, m, o));
        if (lane == 0) redbuf[warp] = m;
    }
    __syncthreads();
    const float m = fmaxf(redbuf[0], redbuf[1]);
    float p = 0.f;
    if (tid < 64) {
        p = (tid < nn) ? expf(x - m) : 0.f;
        float ssum = p;
        #pragma unroll
        for (int o = 16; o; o >>= 1) ssum += __shfl_xor_sync(0xffffffffu, ssum, o);
        if (lane == 0) redbuf[4 + warp] = ssum;
    }
    __syncthreads();
    const float inv = 1.f / (redbuf[4] + redbuf[5]);
    if (tid < 64) sc[tid] = p * inv;    // zero for tid >= nn
    __syncthreads();

    // Output: thread tid owns column tid; unroll x8 with clamped row indices.
    // Weights sc[j+u] are 0 for j+u >= nn, so clamped rows contribute nothing.
    const float* vbase = g_v + (size_t)s * HDIM + tid;
    const int jmax = nn - 1;
    float acc = 0.f;
    for (int j = 0; j < nn; j += 8) {
        float w[8], v[8];
        #pragma unroll
        for (int u = 0; u < 8; u++) {
            int jj = min(j + u, jmax);
            w[u] = sc[j + u];
            v[u] = vbase[(size_t)jj * HDIM];
        }
        #pragma unroll
        for (int u = 0; u < 8; u++) acc = fmaf(w[u], v[u], acc);
    }
    out[(size_t)i * HDIM + tid] = acc;
}

// ---------------------------------------------------------------------------
extern "C" void kernel_launch(void* const* d_in, const int* in_sizes, int n_in,
                              void* d_out, int out_size)
{
    const float* enc    = (const float*)d_in[0];
    const float* social = (const float*)d_in[1];
    const int*   starts = (const int*)  d_in[2];
    const int*   ends   = (const int*)  d_in[3];
    const float* Wq     = (const float*)d_in[4];
    const float* bq     = (const float*)d_in[5];
    const float* Wk     = (const float*)d_in[6];
    const float* bk     = (const float*)d_in[7];
    const float* Wv     = (const float*)d_in[8];
    const float* bv     = (const float*)d_in[9];
    float* out = (float*)d_out;

    const int B = in_sizes[0] / HDIM;
    const int N = in_sizes[1] / HDIM;

    __nv_bfloat16 *kthi, *ktlo, *vthi, *vtlo, *qthi, *qtlo;
    cudaGetSymbolAddress((void**)&kthi, g_wkt_hi);
    cudaGetSymbolAddress((void**)&ktlo, g_wkt_lo);
    cudaGetSymbolAddress((void**)&vthi, g_wvt_hi);
    cudaGetSymbolAddress((void**)&vtlo, g_wvt_lo);
    cudaGetSymbolAddress((void**)&qthi, g_wqt_hi);
    cudaGetSymbolAddress((void**)&qtlo, g_wqt_lo);

    cudaFuncSetAttribute(kv_mma_kernel, cudaFuncAttributeMaxDynamicSharedMemorySize, SMEM_BYTES);
    cudaFuncSetAttribute(q_mma_kernel,  cudaFuncAttributeMaxDynamicSharedMemorySize, SMEM_BYTES);

    const float inv_sqrt_d = 1.0f / sqrtf((float)HDIM);

    // 1. Transpose+split Wk, Wv, Wq (tiny)
    split_w_kernel<<<dim3(HDIM, 3), HDIM>>>(Wk, Wv, Wq, kthi, ktlo, vthi, vtlo, qthi, qtlo);
    // 2. K and V via mma.sync bf16 3-split; A split fused in-kernel
    kv_mma_kernel<<<dim3(HDIM / 128, N / 128, 2), 256, SMEM_BYTES>>>(social, bk, bv);
    // 3. Q via same mma path (16 CTAs)
    q_mma_kernel<<<dim3(HDIM / 128, B / 128), 256, SMEM_BYTES>>>(enc, bq, inv_sqrt_d);
    // 4. Windowed attention
    attn_kernel<<<B, 256>>>(starts, ends, out);
}

// round 12
// speedup vs baseline: 2.0072x; 1.6673x over previous
#include <cuda_runtime.h>
#include <cuda_fp16.h>
#include <math.h>
#include <math_constants.h>
#include <cstdint>

#define HDIM 256
#define MAXB 1024
#define MAXN 32768

// ---------------------------------------------------------------------------
// Scratch (__device__ globals; no dynamic allocation allowed)
// ---------------------------------------------------------------------------
__device__ float g_q[(size_t)MAXB * HDIM];
__device__ float g_k[(size_t)MAXN * HDIM];
__device__ float g_v[(size_t)MAXN * HDIM];
__device__ __half g_wkt[HDIM * HDIM];   // W^T fp16: [n][k], k contiguous
__device__ __half g_wvt[HDIM * HDIM];
__device__ __half g_wqt[HDIM * HDIM];

// Transpose + fp16-convert the three weight matrices: out[n][k] = fp16(W[k][n])
__global__ void __launch_bounds__(256) convert_w_kernel(
    const float* __restrict__ Wk, const float* __restrict__ Wv, const float* __restrict__ Wq,
    __half* __restrict__ ok, __half* __restrict__ ov, __half* __restrict__ oq)
{
    const int n = blockIdx.x, k = threadIdx.x;
    const float* W = (blockIdx.y == 0) ? Wk : (blockIdx.y == 1 ? Wv : Wq);
    __half* o = (blockIdx.y == 0) ? ok : (blockIdx.y == 1 ? ov : oq);
    o[n * HDIM + k] = __float2half(W[k * HDIM + n]);
}

// ---------------------------------------------------------------------------
// Shared GEMM tile body: C[128,128] tile = relu(A_fp32 @ W16^T + bias)*scale
// Single fp16 mma.sync.m16n8k16, cp.async double buffered, in-register A cvt.
// 256 threads, 8 warps = 4(m) x 2(n); warp tile 32x64.
// ---------------------------------------------------------------------------
#define KC 64                         // K-chunk
#define NCHUNK (HDIM / KC)            // 4
#define SROWF 68                      // fp32 A smem row stride (floats); 272 B
#define SROWB 72                      // fp16 B smem row stride (elems); 144 B
#define A_TILE_BYTES (128 * SROWF * 4)        // 34816
#define B_TILE_BYTES (128 * SROWB * 2)        // 18432
#define STAGE_BYTES (A_TILE_BYTES + B_TILE_BYTES)   // 53248
#define SMEM_BYTES (2 * STAGE_BYTES)                // 106496 (2 CTAs/SM: 213KB < 227KB)

__device__ __forceinline__ uint32_t lds32h(const __half* p, int elem_off) {
    return *(const uint32_t*)(p + elem_off);
}
__device__ __forceinline__ void mma_f16(float* d, const uint32_t* a, uint32_t b0, uint32_t b1) {
    asm volatile(
        "mma.sync.aligned.m16n8k16.row.col.f32.f16.f16.f32 "
        "{%0,%1,%2,%3}, {%4,%5,%6,%7}, {%8,%9}, {%0,%1,%2,%3};\n"
        : "+f"(d[0]), "+f"(d[1]), "+f"(d[2]), "+f"(d[3])
        : "r"(a[0]), "r"(a[1]), "r"(a[2]), "r"(a[3]), "r"(b0), "r"(b1));
}
__device__ __forceinline__ void cp_async16(uint32_t smem_dst, const void* gsrc) {
    asm volatile("cp.async.cg.shared.global [%0], [%1], 16;\n" :: "r"(smem_dst), "l"(gsrc));
}
__device__ __forceinline__ uint32_t cvt2(float2 f) {
    __half2 h = __floats2half2_rn(f.x, f.y);
    return *reinterpret_cast<uint32_t*>(&h);
}

__device__ __forceinline__ void gemm_tile_body(
    const float* __restrict__ gA,
    const __half* __restrict__ gB,
    const float* __restrict__ bias, float* __restrict__ C, float scale,
    int bm, int bn, char* smraw)
{
    const int tid = threadIdx.x;
    const int wid = tid >> 5;
    const int lane = tid & 31;
    const int grp = lane >> 2;      // 0..7
    const int qid = lane & 3;       // 0..3
    const int warp_m = wid & 3;     // 4 warps along m (32 rows each)
    const int warp_n = wid >> 2;    // 2 warps along n (64 cols each)

    uint32_t smem_u32;
    {
        uint64_t t = __cvta_generic_to_shared(smraw);
        smem_u32 = (uint32_t)t;
    }

    auto prefetch = [&](int s, int c) {
        uint32_t stage = smem_u32 + s * STAGE_BYTES;
        // A: fp32, 128 rows x 64 floats = 2048 segs of 16B -> 8 per thread
        const float* srcA = gA + (size_t)(bm * 128) * HDIM + c * KC;
        #pragma unroll
        for (int u = 0; u < 8; u++) {
            int seg = u * 256 + tid;
            int row = seg >> 4, cs = seg & 15;
            cp_async16(stage + row * (SROWF * 4) + cs * 16,
                       srcA + (size_t)row * HDIM + cs * 4);
        }
        // B: fp16, 128 rows x 64 elems = 1024 segs of 16B -> 4 per thread
        const __half* srcB = gB + (size_t)(bn * 128) * HDIM + c * KC;
        uint32_t dstb = stage + A_TILE_BYTES;
        #pragma unroll
        for (int u = 0; u < 4; u++) {
            int seg = u * 256 + tid;
            int row = seg >> 3, cs = seg & 7;
            cp_async16(dstb + row * (SROWB * 2) + cs * 16,
                       srcB + (size_t)row * HDIM + cs * 8);
        }
        asm volatile("cp.async.commit_group;\n");
    };

    float acc[2][8][4] = {};

    prefetch(0, 0);

    for (int c = 0; c < NCHUNK; c++) {
        if (c + 1 < NCHUNK) {
            prefetch((c + 1) & 1, c + 1);
            asm volatile("cp.async.wait_group 1;\n");
        } else {
            asm volatile("cp.async.wait_group 0;\n");
        }
        __syncthreads();

        const char* st = smraw + (c & 1) * STAGE_BYTES;
        const float* sA = (const float*)st;
        const __half* sB = (const __half*)(st + A_TILE_BYTES);

        #pragma unroll
        for (int ks = 0; ks < KC / 16; ks++) {
            const int k0 = ks * 16;
            uint32_t af[2][4];
            #pragma unroll
            for (int mi = 0; mi < 2; mi++) {
                const float* a0 = sA + (warp_m * 32 + mi * 16 + grp) * SROWF + k0 + 2 * qid;
                af[mi][0] = cvt2(*(const float2*)(a0));              // row, k
                af[mi][1] = cvt2(*(const float2*)(a0 + 8 * SROWF));  // row+8, k
                af[mi][2] = cvt2(*(const float2*)(a0 + 8));          // row, k+8
                af[mi][3] = cvt2(*(const float2*)(a0 + 8 * SROWF + 8));
            }
            #pragma unroll
            for (int nb = 0; nb < 8; nb++) {
                const int bbase = (warp_n * 64 + nb * 8 + grp) * SROWB + k0 + 2 * qid;
                uint32_t b0 = lds32h(sB, bbase), b1 = lds32h(sB, bbase + 8);
                #pragma unroll
                for (int mi = 0; mi < 2; mi++)
                    mma_f16(acc[mi][nb], af[mi], b0, b1);
            }
        }
        __syncthreads();   // readers done before next iteration's prefetch overwrites
    }

    // Epilogue: bias + relu (+ post-relu scale), fp32 stores.
    #pragma unroll
    for (int mi = 0; mi < 2; mi++) {
        const int row = bm * 128 + warp_m * 32 + mi * 16 + grp;
        #pragma unroll
        for (int nb = 0; nb < 8; nb++) {
            const int col = bn * 128 + warp_n * 64 + nb * 8 + 2 * qid;
            float2 bz = *(const float2*)(bias + col);
            float2 o0, o1;
            o0.x = fmaxf(acc[mi][nb][0] + bz.x, 0.f) * scale;
            o0.y = fmaxf(acc[mi][nb][1] + bz.y, 0.f) * scale;
            o1.x = fmaxf(acc[mi][nb][2] + bz.x, 0.f) * scale;
            o1.y = fmaxf(acc[mi][nb][3] + bz.y, 0.f) * scale;
            *(float2*)(C + (size_t)row * HDIM + col) = o0;
            *(float2*)(C + (size_t)(row + 8) * HDIM + col) = o1;
        }
    }
}

// K/V wrapper: grid (2 n-tiles, 256 m-tiles, 2 mats); 2 CTAs/SM
__global__ void __launch_bounds__(256, 2) kv_mma_kernel(
    const float* __restrict__ gA,
    const float* __restrict__ bk, const float* __restrict__ bv)
{
    extern __shared__ char smraw[];
    const int mat = blockIdx.z;
    gemm_tile_body(gA, mat ? g_wvt : g_wkt,
                   mat ? bv : bk, mat ? g_v : g_k, 1.0f,
                   blockIdx.y, blockIdx.x, smraw);
}

// Q wrapper: grid (2 n-tiles, 8 m-tiles); post-ReLU scale = 1/sqrt(d)
__global__ void __launch_bounds__(256, 2) q_mma_kernel(
    const float* __restrict__ gA, const float* __restrict__ bq, float scale)
{
    extern __shared__ char smraw[];
    gemm_tile_body(gA, g_wqt, bq, g_q, scale, blockIdx.y, blockIdx.x, smraw);
}

// ---------------------------------------------------------------------------
// Windowed attention, MLP-optimized (unchanged from R11 — measured 17.8us).
// ---------------------------------------------------------------------------
__global__ void __launch_bounds__(256) attn_kernel(
    const int* __restrict__ starts, const int* __restrict__ ends, float* __restrict__ out)
{
    const int i = blockIdx.x;
    const int tid = threadIdx.x;
    const int warp = tid >> 5, lane = tid & 31;
    __shared__ float qs[HDIM];
    __shared__ float sc[72];     // scores; entries >= nn stay 0
    __shared__ float redbuf[8];

    qs[tid] = g_q[(size_t)i * HDIM + tid];
    if (tid < 72) sc[tid] = 0.f;
    const int s = starts[i];
    const int nn = ends[i] - s;   // 1..63
    __syncthreads();

    // Scores: warp w handles neighbors w, w+8, ... Lane owns 8 contiguous floats.
    for (int j = warp; j < nn; j += 8) {
        const float4* krow = (const float4*)(g_k + (size_t)(s + j) * HDIM) + lane * 2;
        float4 k0 = krow[0], k1 = krow[1];
        const float4* qrow = (const float4*)qs + lane * 2;
        float4 q0 = qrow[0], q1 = qrow[1];
        float acc = k0.x * q0.x;
        acc = fmaf(k0.y, q0.y, acc);
        acc = fmaf(k0.z, q0.z, acc);
        acc = fmaf(k0.w, q0.w, acc);
        acc = fmaf(k1.x, q1.x, acc);
        acc = fmaf(k1.y, q1.y, acc);
        acc = fmaf(k1.z, q1.z, acc);
        acc = fmaf(k1.w, q1.w, acc);
        #pragma unroll
        for (int o = 16; o; o >>= 1) acc += __shfl_xor_sync(0xffffffffu, acc, o);
        if (lane == 0) sc[j] = acc;
    }
    __syncthreads();

    // Softmax over sc[0..nn) — threads 0..63 (2 warps).
    float x = -CUDART_INF_F;
    if (tid < 64) {
        x = (tid < nn) ? sc[tid] : -CUDART_INF_F;
        float m = x;
        #pragma unroll
        for (int o = 16; o; o >>= 1) m = fmaxf(m, __shfl_xor_sync(0xffffffffu, m, o));
        if (lane == 0) redbuf[warp] = m;
    }
    __syncthreads();
    const float m = fmaxf(redbuf[0], redbuf[1]);
    float p = 0.f;
    if (tid < 64) {
        p = (tid < nn) ? expf(x - m) : 0.f;
        float ssum = p;
        #pragma unroll
        for (int o = 16; o; o >>= 1) ssum += __shfl_xor_sync(0xffffffffu, ssum, o);
        if (lane == 0) redbuf[4 + warp] = ssum;
    }
    __syncthreads();
    const float inv = 1.f / (redbuf[4] + redbuf[5]);
    if (tid < 64) sc[tid] = p * inv;    // zero for tid >= nn
    __syncthreads();

    // Output: thread tid owns column tid; unroll x8 with clamped row indices.
    const float* vbase = g_v + (size_t)s * HDIM + tid;
    const int jmax = nn - 1;
    float acc = 0.f;
    for (int j = 0; j < nn; j += 8) {
        float w[8], v[8];
        #pragma unroll
        for (int u = 0; u < 8; u++) {
            int jj = min(j + u, jmax);
            w[u] = sc[j + u];
            v[u] = vbase[(size_t)jj * HDIM];
        }
        #pragma unroll
        for (int u = 0; u < 8; u++) acc = fmaf(w[u], v[u], acc);
    }
    out[(size_t)i * HDIM + tid] = acc;
}

// ---------------------------------------------------------------------------
extern "C" void kernel_launch(void* const* d_in, const int* in_sizes, int n_in,
                              void* d_out, int out_size)
{
    const float* enc    = (const float*)d_in[0];
    const float* social = (const float*)d_in[1];
    const int*   starts = (const int*)  d_in[2];
    const int*   ends   = (const int*)  d_in[3];
    const float* Wq     = (const float*)d_in[4];
    const float* bq     = (const float*)d_in[5];
    const float* Wk     = (const float*)d_in[6];
    const float* bk     = (const float*)d_in[7];
    const float* Wv     = (const float*)d_in[8];
    const float* bv     = (const float*)d_in[9];
    float* out = (float*)d_out;

    const int B = in_sizes[0] / HDIM;
    const int N = in_sizes[1] / HDIM;

    __half *wk16, *wv16, *wq16;
    cudaGetSymbolAddress((void**)&wk16, g_wkt);
    cudaGetSymbolAddress((void**)&wv16, g_wvt);
    cudaGetSymbolAddress((void**)&wq16, g_wqt);

    cudaFuncSetAttribute(kv_mma_kernel, cudaFuncAttributeMaxDynamicSharedMemorySize, SMEM_BYTES);
    cudaFuncSetAttribute(q_mma_kernel,  cudaFuncAttributeMaxDynamicSharedMemorySize, SMEM_BYTES);

    const float inv_sqrt_d = 1.0f / sqrtf((float)HDIM);

    // 1. Transpose+convert Wk, Wv, Wq to fp16 (tiny)
    convert_w_kernel<<<dim3(HDIM, 3), HDIM>>>(Wk, Wv, Wq, wk16, wv16, wq16);
    // 2. K and V via single-fp16 mma.sync; A cvt fused in-kernel
    kv_mma_kernel<<<dim3(HDIM / 128, N / 128, 2), 256, SMEM_BYTES>>>(social, bk, bv);
    // 3. Q via same mma path (16 CTAs)
    q_mma_kernel<<<dim3(HDIM / 128, B / 128), 256, SMEM_BYTES>>>(enc, bq, inv_sqrt_d);
    // 4. Windowed attention
    attn_kernel<<<B, 256>>>(starts, ends, out);
}

// round 13
// speedup vs baseline: 2.1174x; 1.0549x over previous
#include <cuda_runtime.h>
#include <cuda_fp16.h>
#include <math.h>
#include <math_constants.h>
#include <cstdint>

#define HDIM 256
#define MAXB 1024
#define MAXN 32768

// ---------------------------------------------------------------------------
// Scratch (__device__ globals; no dynamic allocation allowed)
// ---------------------------------------------------------------------------
__device__ float g_q[(size_t)MAXB * HDIM];
__device__ float g_k[(size_t)MAXN * HDIM];
__device__ float g_v[(size_t)MAXN * HDIM];
__device__ __half g_wkt[HDIM * HDIM];   // W^T fp16: [n][k], k contiguous
__device__ __half g_wvt[HDIM * HDIM];
__device__ __half g_wqt[HDIM * HDIM];

// Transpose + fp16-convert the three weight matrices: out[n][k] = fp16(W[k][n])
__global__ void __launch_bounds__(256) convert_w_kernel(
    const float* __restrict__ Wk, const float* __restrict__ Wv, const float* __restrict__ Wq,
    __half* __restrict__ ok, __half* __restrict__ ov, __half* __restrict__ oq)
{
    const int n = blockIdx.x, k = threadIdx.x;
    const float* W = (blockIdx.y == 0) ? Wk : (blockIdx.y == 1 ? Wv : Wq);
    __half* o = (blockIdx.y == 0) ? ok : (blockIdx.y == 1 ? ov : oq);
    o[n * HDIM + k] = __float2half(W[k * HDIM + n]);
}

// ---------------------------------------------------------------------------
// Shared GEMM tile body: C[128,128] tile = relu(A_fp32 @ W16^T + bias)*scale
// Single fp16 mma.sync.m16n8k16, cp.async double buffered, in-register A cvt.
// 256 threads, 8 warps = 4(m) x 2(n); warp tile 32x64.
// ---------------------------------------------------------------------------
#define KC 64                         // K-chunk
#define NCHUNK (HDIM / KC)            // 4
#define SROWF 68                      // fp32 A smem row stride (floats); 272 B
#define SROWB 72                      // fp16 B smem row stride (elems); 144 B
#define A_TILE_BYTES (128 * SROWF * 4)        // 34816
#define B_TILE_BYTES (128 * SROWB * 2)        // 18432
#define STAGE_BYTES (A_TILE_BYTES + B_TILE_BYTES)   // 53248
#define SMEM_BYTES (2 * STAGE_BYTES)                // 106496 (2 CTAs/SM)

__device__ __forceinline__ uint32_t lds32h(const __half* p, int elem_off) {
    return *(const uint32_t*)(p + elem_off);
}
__device__ __forceinline__ void mma_f16(float* d, const uint32_t* a, uint32_t b0, uint32_t b1) {
    asm volatile(
        "mma.sync.aligned.m16n8k16.row.col.f32.f16.f16.f32 "
        "{%0,%1,%2,%3}, {%4,%5,%6,%7}, {%8,%9}, {%0,%1,%2,%3};\n"
        : "+f"(d[0]), "+f"(d[1]), "+f"(d[2]), "+f"(d[3])
        : "r"(a[0]), "r"(a[1]), "r"(a[2]), "r"(a[3]), "r"(b0), "r"(b1));
}
__device__ __forceinline__ void cp_async16(uint32_t smem_dst, const void* gsrc) {
    asm volatile("cp.async.cg.shared.global [%0], [%1], 16;\n" :: "r"(smem_dst), "l"(gsrc));
}
__device__ __forceinline__ uint32_t cvt2(float2 f) {
    __half2 h = __floats2half2_rn(f.x, f.y);
    return *reinterpret_cast<uint32_t*>(&h);
}

__device__ __forceinline__ void gemm_tile_body(
    const float* __restrict__ gA,
    const __half* __restrict__ gB,
    const float* __restrict__ bias, float* __restrict__ C, float scale,
    int bm, int bn, char* smraw)
{
    const int tid = threadIdx.x;
    const int wid = tid >> 5;
    const int lane = tid & 31;
    const int grp = lane >> 2;      // 0..7
    const int qid = lane & 3;       // 0..3
    const int warp_m = wid & 3;     // 4 warps along m (32 rows each)
    const int warp_n = wid >> 2;    // 2 warps along n (64 cols each)

    uint32_t smem_u32;
    {
        uint64_t t = __cvta_generic_to_shared(smraw);
        smem_u32 = (uint32_t)t;
    }

    auto prefetch = [&](int s, int c) {
        uint32_t stage = smem_u32 + s * STAGE_BYTES;
        const float* srcA = gA + (size_t)(bm * 128) * HDIM + c * KC;
        #pragma unroll
        for (int u = 0; u < 8; u++) {
            int seg = u * 256 + tid;
            int row = seg >> 4, cs = seg & 15;
            cp_async16(stage + row * (SROWF * 4) + cs * 16,
                       srcA + (size_t)row * HDIM + cs * 4);
        }
        const __half* srcB = gB + (size_t)(bn * 128) * HDIM + c * KC;
        uint32_t dstb = stage + A_TILE_BYTES;
        #pragma unroll
        for (int u = 0; u < 4; u++) {
            int seg = u * 256 + tid;
            int row = seg >> 3, cs = seg & 7;
            cp_async16(dstb + row * (SROWB * 2) + cs * 16,
                       srcB + (size_t)row * HDIM + cs * 8);
        }
        asm volatile("cp.async.commit_group;\n");
    };

    float acc[2][8][4] = {};

    prefetch(0, 0);

    for (int c = 0; c < NCHUNK; c++) {
        if (c + 1 < NCHUNK) {
            prefetch((c + 1) & 1, c + 1);
            asm volatile("cp.async.wait_group 1;\n");
        } else {
            asm volatile("cp.async.wait_group 0;\n");
        }
        __syncthreads();

        const char* st = smraw + (c & 1) * STAGE_BYTES;
        const float* sA = (const float*)st;
        const __half* sB = (const __half*)(st + A_TILE_BYTES);

        #pragma unroll
        for (int ks = 0; ks < KC / 16; ks++) {
            const int k0 = ks * 16;
            uint32_t af[2][4];
            #pragma unroll
            for (int mi = 0; mi < 2; mi++) {
                const float* a0 = sA + (warp_m * 32 + mi * 16 + grp) * SROWF + k0 + 2 * qid;
                af[mi][0] = cvt2(*(const float2*)(a0));              // row, k
                af[mi][1] = cvt2(*(const float2*)(a0 + 8 * SROWF));  // row+8, k
                af[mi][2] = cvt2(*(const float2*)(a0 + 8));          // row, k+8
                af[mi][3] = cvt2(*(const float2*)(a0 + 8 * SROWF + 8));
            }
            #pragma unroll
            for (int nb = 0; nb < 8; nb++) {
                const int bbase = (warp_n * 64 + nb * 8 + grp) * SROWB + k0 + 2 * qid;
                uint32_t b0 = lds32h(sB, bbase), b1 = lds32h(sB, bbase + 8);
                #pragma unroll
                for (int mi = 0; mi < 2; mi++)
                    mma_f16(acc[mi][nb], af[mi], b0, b1);
            }
        }
        __syncthreads();   // readers done before next iteration's prefetch overwrites
    }

    // Epilogue: bias + relu (+ post-relu scale), fp32 stores.
    #pragma unroll
    for (int mi = 0; mi < 2; mi++) {
        const int row = bm * 128 + warp_m * 32 + mi * 16 + grp;
        #pragma unroll
        for (int nb = 0; nb < 8; nb++) {
            const int col = bn * 128 + warp_n * 64 + nb * 8 + 2 * qid;
            float2 bz = *(const float2*)(bias + col);
            float2 o0, o1;
            o0.x = fmaxf(acc[mi][nb][0] + bz.x, 0.f) * scale;
            o0.y = fmaxf(acc[mi][nb][1] + bz.y, 0.f) * scale;
            o1.x = fmaxf(acc[mi][nb][2] + bz.x, 0.f) * scale;
            o1.y = fmaxf(acc[mi][nb][3] + bz.y, 0.f) * scale;
            *(float2*)(C + (size_t)row * HDIM + col) = o0;
            *(float2*)(C + (size_t)(row + 8) * HDIM + col) = o1;
        }
    }
}

// Fused K/V/Q GEMM: grid (2 n-tiles, 256 m-tiles, 3 planes).
// z=0: K, z=1: V, z=2: Q (active only for bm < qm_tiles; others exit).
__global__ void __launch_bounds__(256, 2) fused_mma_kernel(
    const float* __restrict__ social, const float* __restrict__ enc,
    const float* __restrict__ bk, const float* __restrict__ bv,
    const float* __restrict__ bq, float inv_sqrt_d, int qm_tiles)
{
    extern __shared__ char smraw[];
    const int z = blockIdx.z;
    if (z == 2) {
        if (blockIdx.y >= qm_tiles) return;
        gemm_tile_body(enc, g_wqt, bq, g_q, inv_sqrt_d, blockIdx.y, blockIdx.x, smraw);
    } else {
        gemm_tile_body(social, z ? g_wvt : g_wkt, z ? bv : bk, z ? g_v : g_k, 1.0f,
                       blockIdx.y, blockIdx.x, smraw);
    }
}

// ---------------------------------------------------------------------------
// Windowed attention. Score phase: unroll x2 over K rows (MLP 4).
// V phase: unroll x8, clamped rows, zero-padded weights (nn <= 63).
// ---------------------------------------------------------------------------
__global__ void __launch_bounds__(256) attn_kernel(
    const int* __restrict__ starts, const int* __restrict__ ends, float* __restrict__ out)
{
    const int i = blockIdx.x;
    const int tid = threadIdx.x;
    const int warp = tid >> 5, lane = tid & 31;
    __shared__ float qs[HDIM];
    __shared__ float sc[72];     // scores; entries >= nn stay 0
    __shared__ float redbuf[8];

    qs[tid] = g_q[(size_t)i * HDIM + tid];
    if (tid < 72) sc[tid] = 0.f;
    const int s = starts[i];
    const int nn = ends[i] - s;   // 1..63
    __syncthreads();

    // Scores: warp w handles rows w, w+8, ...; unroll x2 (rows j, j+8 together).
    {
        const float4* qrow = (const float4*)qs + lane * 2;
        const float4 q0 = qrow[0], q1 = qrow[1];
        int j = warp;
        for (; j + 8 < nn; j += 16) {
            const float4* ka = (const float4*)(g_k + (size_t)(s + j) * HDIM) + lane * 2;
            const float4* kb = (const float4*)(g_k + (size_t)(s + j + 8) * HDIM) + lane * 2;
            float4 a0 = ka[0], a1 = ka[1];
            float4 b0 = kb[0], b1 = kb[1];
            float accA = a0.x * q0.x;
            float accB = b0.x * q0.x;
            accA = fmaf(a0.y, q0.y, accA);  accB = fmaf(b0.y, q0.y, accB);
            accA = fmaf(a0.z, q0.z, accA);  accB = fmaf(b0.z, q0.z, accB);
            accA = fmaf(a0.w, q0.w, accA);  accB = fmaf(b0.w, q0.w, accB);
            accA = fmaf(a1.x, q1.x, accA);  accB = fmaf(b1.x, q1.x, accB);
            accA = fmaf(a1.y, q1.y, accA);  accB = fmaf(b1.y, q1.y, accB);
            accA = fmaf(a1.z, q1.z, accA);  accB = fmaf(b1.z, q1.z, accB);
            accA = fmaf(a1.w, q1.w, accA);  accB = fmaf(b1.w, q1.w, accB);
            #pragma unroll
            for (int o = 16; o; o >>= 1) {
                accA += __shfl_xor_sync(0xffffffffu, accA, o);
                accB += __shfl_xor_sync(0xffffffffu, accB, o);
            }
            if (lane == 0) { sc[j] = accA; sc[j + 8] = accB; }
        }
        if (j < nn) {
            const float4* krow = (const float4*)(g_k + (size_t)(s + j) * HDIM) + lane * 2;
            float4 k0 = krow[0], k1 = krow[1];
            float acc = k0.x * q0.x;
            acc = fmaf(k0.y, q0.y, acc);
            acc = fmaf(k0.z, q0.z, acc);
            acc = fmaf(k0.w, q0.w, acc);
            acc = fmaf(k1.x, q1.x, acc);
            acc = fmaf(k1.y, q1.y, acc);
            acc = fmaf(k1.z, q1.z, acc);
            acc = fmaf(k1.w, q1.w, acc);
            #pragma unroll
            for (int o = 16; o; o >>= 1) acc += __shfl_xor_sync(0xffffffffu, acc, o);
            if (lane == 0) sc[j] = acc;
        }
    }
    __syncthreads();

    // Softmax over sc[0..nn) — threads 0..63 (2 warps).
    float x = -CUDART_INF_F;
    if (tid < 64) {
        x = (tid < nn) ? sc[tid] : -CUDART_INF_F;
        float m = x;
        #pragma unroll
        for (int o = 16; o; o >>= 1) m = fmaxf(m, __shfl_xor_sync(0xffffffffu, m, o));
        if (lane == 0) redbuf[warp] = m;
    }
    __syncthreads();
    const float m = fmaxf(redbuf[0], redbuf[1]);
    float p = 0.f;
    if (tid < 64) {
        p = (tid < nn) ? expf(x - m) : 0.f;
        float ssum = p;
        #pragma unroll
        for (int o = 16; o; o >>= 1) ssum += __shfl_xor_sync(0xffffffffu, ssum, o);
        if (lane == 0) redbuf[4 + warp] = ssum;
    }
    __syncthreads();
    const float inv = 1.f / (redbuf[4] + redbuf[5]);
    if (tid < 64) sc[tid] = p * inv;    // zero for tid >= nn
    __syncthreads();

    // Output: thread tid owns column tid; unroll x8 with clamped row indices.
    const float* vbase = g_v + (size_t)s * HDIM + tid;
    const int jmax = nn - 1;
    float acc = 0.f;
    for (int j = 0; j < nn; j += 8) {
        float w[8], v[8];
        #pragma unroll
        for (int u = 0; u < 8; u++) {
            int jj = min(j + u, jmax);
            w[u] = sc[j + u];
            v[u] = vbase[(size_t)jj * HDIM];
        }
        #pragma unroll
        for (int u = 0; u < 8; u++) acc = fmaf(w[u], v[u], acc);
    }
    out[(size_t)i * HDIM + tid] = acc;
}

// ---------------------------------------------------------------------------
extern "C" void kernel_launch(void* const* d_in, const int* in_sizes, int n_in,
                              void* d_out, int out_size)
{
    const float* enc    = (const float*)d_in[0];
    const float* social = (const float*)d_in[1];
    const int*   starts = (const int*)  d_in[2];
    const int*   ends   = (const int*)  d_in[3];
    const float* Wq     = (const float*)d_in[4];
    const float* bq     = (const float*)d_in[5];
    const float* Wk     = (const float*)d_in[6];
    const float* bk     = (const float*)d_in[7];
    const float* Wv     = (const float*)d_in[8];
    const float* bv     = (const float*)d_in[9];
    float* out = (float*)d_out;

    const int B = in_sizes[0] / HDIM;
    const int N = in_sizes[1] / HDIM;

    __half *wk16, *wv16, *wq16;
    cudaGetSymbolAddress((void**)&wk16, g_wkt);
    cudaGetSymbolAddress((void**)&wv16, g_wvt);
    cudaGetSymbolAddress((void**)&wq16, g_wqt);

    cudaFuncSetAttribute(fused_mma_kernel, cudaFuncAttributeMaxDynamicSharedMemorySize, SMEM_BYTES);

    const float inv_sqrt_d = 1.0f / sqrtf((float)HDIM);

    // 1. Transpose+convert Wk, Wv, Wq to fp16 (tiny)
    convert_w_kernel<<<dim3(HDIM, 3), HDIM>>>(Wk, Wv, Wq, wk16, wv16, wq16);
    // 2. K, V and Q in ONE launch (z=0:K, z=1:V, z=2:Q)
    fused_mma_kernel<<<dim3(HDIM / 128, N / 128, 3), 256, SMEM_BYTES>>>(
        social, enc, bk, bv, bq, inv_sqrt_d, B / 128);
    // 3. Windowed attention
    attn_kernel<<<B, 256>>>(starts, ends, out);
}

// round 14
// speedup vs baseline: 2.1612x; 1.0207x over previous
#include <cuda_runtime.h>
#include <cuda_fp16.h>
#include <math.h>
#include <math_constants.h>
#include <cstdint>

#define HDIM 256
#define MAXB 1024
#define MAXN 32768

// ---------------------------------------------------------------------------
// Scratch (__device__ globals; no dynamic allocation allowed)
// ---------------------------------------------------------------------------
__device__ float g_q[(size_t)MAXB * HDIM];
__device__ float g_k[(size_t)MAXN * HDIM];
__device__ float g_v[(size_t)MAXN * HDIM];
__device__ __half g_wkt[HDIM * HDIM];   // W^T fp16: [n][k], k contiguous
__device__ __half g_wvt[HDIM * HDIM];
__device__ __half g_wqt[HDIM * HDIM];

// Tiled transpose + fp16 convert: out[n][k] = fp16(W[k][n]).
// 32x32 tiles; coalesced reads (n contiguous) and writes (k contiguous).
__global__ void __launch_bounds__(256) convert_w_kernel(
    const float* __restrict__ Wk, const float* __restrict__ Wv, const float* __restrict__ Wq,
    __half* __restrict__ ok, __half* __restrict__ ov, __half* __restrict__ oq)
{
    __shared__ float tile[32][33];
    const float* W = (blockIdx.z == 0) ? Wk : (blockIdx.z == 1 ? Wv : Wq);
    __half* o = (blockIdx.z == 0) ? ok : (blockIdx.z == 1 ? ov : oq);

    const int k0 = blockIdx.y * 32;   // source row block (k)
    const int n0 = blockIdx.x * 32;   // source col block (n)
    const int tx = threadIdx.x & 31;  // 0..31
    const int ty = threadIdx.x >> 5;  // 0..7

    // Read 32x32 fp32 tile, coalesced along n.
    #pragma unroll
    for (int r = 0; r < 32; r += 8)
        tile[ty + r][tx] = W[(size_t)(k0 + ty + r) * HDIM + n0 + tx];
    __syncthreads();

    // Write transposed, coalesced along k (fp16).
    #pragma unroll
    for (int r = 0; r < 32; r += 8)
        o[(size_t)(n0 + ty + r) * HDIM + k0 + tx] = __float2half(tile[tx][ty + r]);
}

// ---------------------------------------------------------------------------
// Shared GEMM tile body: C[128,128] tile = relu(A_fp32 @ W16^T + bias)*scale
// Single fp16 mma.sync.m16n8k16, cp.async double buffered, in-register A cvt.
// 256 threads, 8 warps = 4(m) x 2(n); warp tile 32x64.
// ---------------------------------------------------------------------------
#define KC 64                         // K-chunk
#define NCHUNK (HDIM / KC)            // 4
#define SROWF 68                      // fp32 A smem row stride (floats); 272 B
#define SROWB 72                      // fp16 B smem row stride (elems); 144 B
#define A_TILE_BYTES (128 * SROWF * 4)        // 34816
#define B_TILE_BYTES (128 * SROWB * 2)        // 18432
#define STAGE_BYTES (A_TILE_BYTES + B_TILE_BYTES)   // 53248
#define SMEM_BYTES (2 * STAGE_BYTES)                // 106496 (2 CTAs/SM)

__device__ __forceinline__ uint32_t lds32h(const __half* p, int elem_off) {
    return *(const uint32_t*)(p + elem_off);
}
__device__ __forceinline__ void mma_f16(float* d, const uint32_t* a, uint32_t b0, uint32_t b1) {
    asm volatile(
        "mma.sync.aligned.m16n8k16.row.col.f32.f16.f16.f32 "
        "{%0,%1,%2,%3}, {%4,%5,%6,%7}, {%8,%9}, {%0,%1,%2,%3};\n"
        : "+f"(d[0]), "+f"(d[1]), "+f"(d[2]), "+f"(d[3])
        : "r"(a[0]), "r"(a[1]), "r"(a[2]), "r"(a[3]), "r"(b0), "r"(b1));
}
__device__ __forceinline__ void cp_async16(uint32_t smem_dst, const void* gsrc) {
    asm volatile("cp.async.cg.shared.global [%0], [%1], 16;\n" :: "r"(smem_dst), "l"(gsrc));
}
__device__ __forceinline__ uint32_t cvt2(float2 f) {
    __half2 h = __floats2half2_rn(f.x, f.y);
    return *reinterpret_cast<uint32_t*>(&h);
}

__device__ __forceinline__ void gemm_tile_body(
    const float* __restrict__ gA,
    const __half* __restrict__ gB,
    const float* __restrict__ bias, float* __restrict__ C, float scale,
    int bm, int bn, char* smraw)
{
    const int tid = threadIdx.x;
    const int wid = tid >> 5;
    const int lane = tid & 31;
    const int grp = lane >> 2;      // 0..7
    const int qid = lane & 3;       // 0..3
    const int warp_m = wid & 3;     // 4 warps along m (32 rows each)
    const int warp_n = wid >> 2;    // 2 warps along n (64 cols each)

    uint32_t smem_u32;
    {
        uint64_t t = __cvta_generic_to_shared(smraw);
        smem_u32 = (uint32_t)t;
    }

    auto prefetch = [&](int s, int c) {
        uint32_t stage = smem_u32 + s * STAGE_BYTES;
        const float* srcA = gA + (size_t)(bm * 128) * HDIM + c * KC;
        #pragma unroll
        for (int u = 0; u < 8; u++) {
            int seg = u * 256 + tid;
            int row = seg >> 4, cs = seg & 15;
            cp_async16(stage + row * (SROWF * 4) + cs * 16,
                       srcA + (size_t)row * HDIM + cs * 4);
        }
        const __half* srcB = gB + (size_t)(bn * 128) * HDIM + c * KC;
        uint32_t dstb = stage + A_TILE_BYTES;
        #pragma unroll
        for (int u = 0; u < 4; u++) {
            int seg = u * 256 + tid;
            int row = seg >> 3, cs = seg & 7;
            cp_async16(dstb + row * (SROWB * 2) + cs * 16,
                       srcB + (size_t)row * HDIM + cs * 8);
        }
        asm volatile("cp.async.commit_group;\n");
    };

    float acc[2][8][4] = {};

    prefetch(0, 0);

    for (int c = 0; c < NCHUNK; c++) {
        if (c + 1 < NCHUNK) {
            prefetch((c + 1) & 1, c + 1);
            asm volatile("cp.async.wait_group 1;\n");
        } else {
            asm volatile("cp.async.wait_group 0;\n");
        }
        __syncthreads();

        const char* st = smraw + (c & 1) * STAGE_BYTES;
        const float* sA = (const float*)st;
        const __half* sB = (const __half*)(st + A_TILE_BYTES);

        #pragma unroll
        for (int ks = 0; ks < KC / 16; ks++) {
            const int k0 = ks * 16;
            uint32_t af[2][4];
            #pragma unroll
            for (int mi = 0; mi < 2; mi++) {
                const float* a0 = sA + (warp_m * 32 + mi * 16 + grp) * SROWF + k0 + 2 * qid;
                af[mi][0] = cvt2(*(const float2*)(a0));              // row, k
                af[mi][1] = cvt2(*(const float2*)(a0 + 8 * SROWF));  // row+8, k
                af[mi][2] = cvt2(*(const float2*)(a0 + 8));          // row, k+8
                af[mi][3] = cvt2(*(const float2*)(a0 + 8 * SROWF + 8));
            }
            #pragma unroll
            for (int nb = 0; nb < 8; nb++) {
                const int bbase = (warp_n * 64 + nb * 8 + grp) * SROWB + k0 + 2 * qid;
                uint32_t b0 = lds32h(sB, bbase), b1 = lds32h(sB, bbase + 8);
                #pragma unroll
                for (int mi = 0; mi < 2; mi++)
                    mma_f16(acc[mi][nb], af[mi], b0, b1);
            }
        }
        __syncthreads();   // readers done before next iteration's prefetch overwrites
    }

    // Epilogue: bias + relu (+ post-relu scale), fp32 stores.
    #pragma unroll
    for (int mi = 0; mi < 2; mi++) {
        const int row = bm * 128 + warp_m * 32 + mi * 16 + grp;
        #pragma unroll
        for (int nb = 0; nb < 8; nb++) {
            const int col = bn * 128 + warp_n * 64 + nb * 8 + 2 * qid;
            float2 bz = *(const float2*)(bias + col);
            float2 o0, o1;
            o0.x = fmaxf(acc[mi][nb][0] + bz.x, 0.f) * scale;
            o0.y = fmaxf(acc[mi][nb][1] + bz.y, 0.f) * scale;
            o1.x = fmaxf(acc[mi][nb][2] + bz.x, 0.f) * scale;
            o1.y = fmaxf(acc[mi][nb][3] + bz.y, 0.f) * scale;
            *(float2*)(C + (size_t)row * HDIM + col) = o0;
            *(float2*)(C + (size_t)(row + 8) * HDIM + col) = o1;
        }
    }
}

// Fused K/V/Q GEMM: grid (2 n-tiles, 256 m-tiles, 3 planes).
// z=0: K, z=1: V, z=2: Q (active only for bm < qm_tiles; others exit).
__global__ void __launch_bounds__(256, 2) fused_mma_kernel(
    const float* __restrict__ social, const float* __restrict__ enc,
    const float* __restrict__ bk, const float* __restrict__ bv,
    const float* __restrict__ bq, float inv_sqrt_d, int qm_tiles)
{
    extern __shared__ char smraw[];
    const int z = blockIdx.z;
    if (z == 2) {
        if (blockIdx.y >= qm_tiles) return;
        gemm_tile_body(enc, g_wqt, bq, g_q, inv_sqrt_d, blockIdx.y, blockIdx.x, smraw);
    } else {
        gemm_tile_body(social, z ? g_wvt : g_wkt, z ? bv : bk, z ? g_v : g_k, 1.0f,
                       blockIdx.y, blockIdx.x, smraw);
    }
}

// ---------------------------------------------------------------------------
// Windowed attention. Score phase: unroll x2 over K rows (MLP 4).
// V phase: unroll x8, clamped rows, zero-padded weights (nn <= 63).
// ---------------------------------------------------------------------------
__global__ void __launch_bounds__(256) attn_kernel(
    const int* __restrict__ starts, const int* __restrict__ ends, float* __restrict__ out)
{
    const int i = blockIdx.x;
    const int tid = threadIdx.x;
    const int warp = tid >> 5, lane = tid & 31;
    __shared__ float qs[HDIM];
    __shared__ float sc[72];     // scores; entries >= nn stay 0
    __shared__ float redbuf[8];

    qs[tid] = g_q[(size_t)i * HDIM + tid];
    if (tid < 72) sc[tid] = 0.f;
    const int s = starts[i];
    const int nn = ends[i] - s;   // 1..63
    __syncthreads();

    // Scores: warp w handles rows w, w+8, ...; unroll x2 (rows j, j+8 together).
    {
        const float4* qrow = (const float4*)qs + lane * 2;
        const float4 q0 = qrow[0], q1 = qrow[1];
        int j = warp;
        for (; j + 8 < nn; j += 16) {
            const float4* ka = (const float4*)(g_k + (size_t)(s + j) * HDIM) + lane * 2;
            const float4* kb = (const float4*)(g_k + (size_t)(s + j + 8) * HDIM) + lane * 2;
            float4 a0 = ka[0], a1 = ka[1];
            float4 b0 = kb[0], b1 = kb[1];
            float accA = a0.x * q0.x;
            float accB = b0.x * q0.x;
            accA = fmaf(a0.y, q0.y, accA);  accB = fmaf(b0.y, q0.y, accB);
            accA = fmaf(a0.z, q0.z, accA);  accB = fmaf(b0.z, q0.z, accB);
            accA = fmaf(a0.w, q0.w, accA);  accB = fmaf(b0.w, q0.w, accB);
            accA = fmaf(a1.x, q1.x, accA);  accB = fmaf(b1.x, q1.x, accB);
            accA = fmaf(a1.y, q1.y, accA);  accB = fmaf(b1.y, q1.y, accB);
            accA = fmaf(a1.z, q1.z, accA);  accB = fmaf(b1.z, q1.z, accB);
            accA = fmaf(a1.w, q1.w, accA);  accB = fmaf(b1.w, q1.w, accB);
            #pragma unroll
            for (int o = 16; o; o >>= 1) {
                accA += __shfl_xor_sync(0xffffffffu, accA, o);
                accB += __shfl_xor_sync(0xffffffffu, accB, o);
            }
            if (lane == 0) { sc[j] = accA; sc[j + 8] = accB; }
        }
        if (j < nn) {
            const float4* krow = (const float4*)(g_k + (size_t)(s + j) * HDIM) + lane * 2;
            float4 k0 = krow[0], k1 = krow[1];
            float acc = k0.x * q0.x;
            acc = fmaf(k0.y, q0.y, acc);
            acc = fmaf(k0.z, q0.z, acc);
            acc = fmaf(k0.w, q0.w, acc);
            acc = fmaf(k1.x, q1.x, acc);
            acc = fmaf(k1.y, q1.y, acc);
            acc = fmaf(k1.z, q1.z, acc);
            acc = fmaf(k1.w, q1.w, acc);
            #pragma unroll
            for (int o = 16; o; o >>= 1) acc += __shfl_xor_sync(0xffffffffu, acc, o);
            if (lane == 0) sc[j] = acc;
        }
    }
    __syncthreads();

    // Softmax over sc[0..nn) — threads 0..63 (2 warps).
    float x = -CUDART_INF_F;
    if (tid < 64) {
        x = (tid < nn) ? sc[tid] : -CUDART_INF_F;
        float m = x;
        #pragma unroll
        for (int o = 16; o; o >>= 1) m = fmaxf(m, __shfl_xor_sync(0xffffffffu, m, o));
        if (lane == 0) redbuf[warp] = m;
    }
    __syncthreads();
    const float m = fmaxf(redbuf[0], redbuf[1]);
    float p = 0.f;
    if (tid < 64) {
        p = (tid < nn) ? expf(x - m) : 0.f;
        float ssum = p;
        #pragma unroll
        for (int o = 16; o; o >>= 1) ssum += __shfl_xor_sync(0xffffffffu, ssum, o);
        if (lane == 0) redbuf[4 + warp] = ssum;
    }
    __syncthreads();
    const float inv = 1.f / (redbuf[4] + redbuf[5]);
    if (tid < 64) sc[tid] = p * inv;    // zero for tid >= nn
    __syncthreads();

    // Output: thread tid owns column tid; unroll x8 with clamped row indices.
    const float* vbase = g_v + (size_t)s * HDIM + tid;
    const int jmax = nn - 1;
    float acc = 0.f;
    for (int j = 0; j < nn; j += 8) {
        float w[8], v[8];
        #pragma unroll
        for (int u = 0; u < 8; u++) {
            int jj = min(j + u, jmax);
            w[u] = sc[j + u];
            v[u] = vbase[(size_t)jj * HDIM];
        }
        #pragma unroll
        for (int u = 0; u < 8; u++) acc = fmaf(w[u], v[u], acc);
    }
    out[(size_t)i * HDIM + tid] = acc;
}

// ---------------------------------------------------------------------------
extern "C" void kernel_launch(void* const* d_in, const int* in_sizes, int n_in,
                              void* d_out, int out_size)
{
    const float* enc    = (const float*)d_in[0];
    const float* social = (const float*)d_in[1];
    const int*   starts = (const int*)  d_in[2];
    const int*   ends   = (const int*)  d_in[3];
    const float* Wq     = (const float*)d_in[4];
    const float* bq     = (const float*)d_in[5];
    const float* Wk     = (const float*)d_in[6];
    const float* bk     = (const float*)d_in[7];
    const float* Wv     = (const float*)d_in[8];
    const float* bv     = (const float*)d_in[9];
    float* out = (float*)d_out;

    const int B = in_sizes[0] / HDIM;
    const int N = in_sizes[1] / HDIM;

    __half *wk16, *wv16, *wq16;
    cudaGetSymbolAddress((void**)&wk16, g_wkt);
    cudaGetSymbolAddress((void**)&wv16, g_wvt);
    cudaGetSymbolAddress((void**)&wq16, g_wqt);

    cudaFuncSetAttribute(fused_mma_kernel, cudaFuncAttributeMaxDynamicSharedMemorySize, SMEM_BYTES);

    const float inv_sqrt_d = 1.0f / sqrtf((float)HDIM);

    // 1. Tiled transpose+convert Wk, Wv, Wq to fp16 (coalesced both sides)
    convert_w_kernel<<<dim3(HDIM / 32, HDIM / 32, 3), 256>>>(Wk, Wv, Wq, wk16, wv16, wq16);
    // 2. K, V and Q in ONE launch (z=0:K, z=1:V, z=2:Q)
    fused_mma_kernel<<<dim3(HDIM / 128, N / 128, 3), 256, SMEM_BYTES>>>(
        social, enc, bk, bv, bq, inv_sqrt_d, B / 128);
    // 3. Windowed attention
    attn_kernel<<<B, 256>>>(starts, ends, out);
}

// round 15
// speedup vs baseline: 2.1687x; 1.0035x over previous
#include <cuda_runtime.h>
#include <cuda_fp16.h>
#include <math.h>
#include <math_constants.h>
#include <cstdint>

#define HDIM 256
#define MAXB 1024
#define MAXN 32768

// ---------------------------------------------------------------------------
// Scratch (__device__ globals; no dynamic allocation allowed)
// ---------------------------------------------------------------------------
__device__ float g_q[(size_t)MAXB * HDIM];
__device__ float g_k[(size_t)MAXN * HDIM];
__device__ float g_v[(size_t)MAXN * HDIM];
__device__ __half g_wkt[HDIM * HDIM];   // W^T fp16: [n][k], k contiguous
__device__ __half g_wvt[HDIM * HDIM];
__device__ __half g_wqt[HDIM * HDIM];

// Tiled transpose + fp16 convert: out[n][k] = fp16(W[k][n]).
__global__ void __launch_bounds__(256) convert_w_kernel(
    const float* __restrict__ Wk, const float* __restrict__ Wv, const float* __restrict__ Wq,
    __half* __restrict__ ok, __half* __restrict__ ov, __half* __restrict__ oq)
{
    __shared__ float tile[32][33];
    const float* W = (blockIdx.z == 0) ? Wk : (blockIdx.z == 1 ? Wv : Wq);
    __half* o = (blockIdx.z == 0) ? ok : (blockIdx.z == 1 ? ov : oq);

    const int k0 = blockIdx.y * 32;
    const int n0 = blockIdx.x * 32;
    const int tx = threadIdx.x & 31;
    const int ty = threadIdx.x >> 5;

    #pragma unroll
    for (int r = 0; r < 32; r += 8)
        tile[ty + r][tx] = W[(size_t)(k0 + ty + r) * HDIM + n0 + tx];
    __syncthreads();
    #pragma unroll
    for (int r = 0; r < 32; r += 8)
        o[(size_t)(n0 + ty + r) * HDIM + k0 + tx] = __float2half(tile[tx][ty + r]);
}

// ---------------------------------------------------------------------------
// Shared GEMM tile body: C[128,128] tile = relu(A_fp32 @ W16^T + bias)*scale
// fp16 mma.sync.m16n8k16, cp.async double buffered, in-register A cvt,
// ldmatrix.x4 for B fragments. 256 threads, 8 warps = 4(m) x 2(n).
// ---------------------------------------------------------------------------
#define KC 64                         // K-chunk
#define NCHUNK (HDIM / KC)            // 4
#define SROWF 68                      // fp32 A smem row stride (floats); 272 B
#define SROWB 72                      // fp16 B smem row stride (elems); 144 B
#define A_TILE_BYTES (128 * SROWF * 4)        // 34816
#define B_TILE_BYTES (128 * SROWB * 2)        // 18432
#define STAGE_BYTES (A_TILE_BYTES + B_TILE_BYTES)   // 53248
#define SMEM_BYTES (2 * STAGE_BYTES)                // 106496 (2 CTAs/SM)

__device__ __forceinline__ void mma_f16(float* d, const uint32_t* a, uint32_t b0, uint32_t b1) {
    asm volatile(
        "mma.sync.aligned.m16n8k16.row.col.f32.f16.f16.f32 "
        "{%0,%1,%2,%3}, {%4,%5,%6,%7}, {%8,%9}, {%0,%1,%2,%3};\n"
        : "+f"(d[0]), "+f"(d[1]), "+f"(d[2]), "+f"(d[3])
        : "r"(a[0]), "r"(a[1]), "r"(a[2]), "r"(a[3]), "r"(b0), "r"(b1));
}
__device__ __forceinline__ void ldmatrix_x4(uint32_t& r0, uint32_t& r1, uint32_t& r2, uint32_t& r3,
                                            uint32_t smem_addr) {
    asm volatile("ldmatrix.sync.aligned.m8n8.x4.shared.b16 {%0,%1,%2,%3}, [%4];\n"
                 : "=r"(r0), "=r"(r1), "=r"(r2), "=r"(r3) : "r"(smem_addr));
}
__device__ __forceinline__ void cp_async16(uint32_t smem_dst, const void* gsrc) {
    asm volatile("cp.async.cg.shared.global [%0], [%1], 16;\n" :: "r"(smem_dst), "l"(gsrc));
}
__device__ __forceinline__ uint32_t cvt2(float2 f) {
    __half2 h = __floats2half2_rn(f.x, f.y);
    return *reinterpret_cast<uint32_t*>(&h);
}

__device__ __forceinline__ void gemm_tile_body(
    const float* __restrict__ gA,
    const __half* __restrict__ gB,
    const float* __restrict__ bias, float* __restrict__ C, float scale,
    int bm, int bn, char* smraw)
{
    const int tid = threadIdx.x;
    const int wid = tid >> 5;
    const int lane = tid & 31;
    const int grp = lane >> 2;      // 0..7
    const int qid = lane & 3;       // 0..3
    const int warp_m = wid & 3;     // 4 warps along m (32 rows each)
    const int warp_n = wid >> 2;    // 2 warps along n (64 cols each)

    uint32_t smem_u32;
    {
        uint64_t t = __cvta_generic_to_shared(smraw);
        smem_u32 = (uint32_t)t;
    }

    // ldmatrix per-lane address offset within a (16n x 16k) B block:
    // lanes 0-7: (n=l, k=0); 8-15: (n=l-8, k=8); 16-23: (n=8+l-16, k=0); 24-31: (n=8+l-24, k=8)
    const int ldm_n = ((lane >> 4) & 1) * 8 + (lane & 7);
    const int ldm_k = ((lane >> 3) & 1) * 8;
    const uint32_t ldm_lane_off = (uint32_t)(ldm_n * SROWB + ldm_k) * 2;

    auto prefetch = [&](int s, int c) {
        uint32_t stage = smem_u32 + s * STAGE_BYTES;
        const float* srcA = gA + (size_t)(bm * 128) * HDIM + c * KC;
        #pragma unroll
        for (int u = 0; u < 8; u++) {
            int seg = u * 256 + tid;
            int row = seg >> 4, cs = seg & 15;
            cp_async16(stage + row * (SROWF * 4) + cs * 16,
                       srcA + (size_t)row * HDIM + cs * 4);
        }
        const __half* srcB = gB + (size_t)(bn * 128) * HDIM + c * KC;
        uint32_t dstb = stage + A_TILE_BYTES;
        #pragma unroll
        for (int u = 0; u < 4; u++) {
            int seg = u * 256 + tid;
            int row = seg >> 3, cs = seg & 7;
            cp_async16(dstb + row * (SROWB * 2) + cs * 16,
                       srcB + (size_t)row * HDIM + cs * 8);
        }
        asm volatile("cp.async.commit_group;\n");
    };

    float acc[2][8][4] = {};

    prefetch(0, 0);

    for (int c = 0; c < NCHUNK; c++) {
        if (c + 1 < NCHUNK) {
            prefetch((c + 1) & 1, c + 1);
            asm volatile("cp.async.wait_group 1;\n");
        } else {
            asm volatile("cp.async.wait_group 0;\n");
        }
        __syncthreads();

        const char* st = smraw + (c & 1) * STAGE_BYTES;
        const float* sA = (const float*)st;
        const uint32_t sB_u32 = smem_u32 + (c & 1) * STAGE_BYTES + A_TILE_BYTES;

        #pragma unroll
        for (int ks = 0; ks < KC / 16; ks++) {
            const int k0 = ks * 16;
            uint32_t af[2][4];
            #pragma unroll
            for (int mi = 0; mi < 2; mi++) {
                const float* a0 = sA + (warp_m * 32 + mi * 16 + grp) * SROWF + k0 + 2 * qid;
                af[mi][0] = cvt2(*(const float2*)(a0));              // row, k
                af[mi][1] = cvt2(*(const float2*)(a0 + 8 * SROWF));  // row+8, k
                af[mi][2] = cvt2(*(const float2*)(a0 + 8));          // row, k+8
                af[mi][3] = cvt2(*(const float2*)(a0 + 8 * SROWF + 8));
            }
            #pragma unroll
            for (int nbp = 0; nbp < 4; nbp++) {   // pairs of nb tiles: 16 n-rows each
                uint32_t baddr = sB_u32 + ldm_lane_off
                               + (uint32_t)((warp_n * 64 + nbp * 16) * SROWB + k0) * 2;
                uint32_t r0, r1, r2, r3;
                ldmatrix_x4(r0, r1, r2, r3, baddr);
                #pragma unroll
                for (int mi = 0; mi < 2; mi++) {
                    mma_f16(acc[mi][nbp * 2 + 0], af[mi], r0, r1);
                    mma_f16(acc[mi][nbp * 2 + 1], af[mi], r2, r3);
                }
            }
        }
        __syncthreads();   // readers done before next iteration's prefetch overwrites
    }

    // Epilogue: bias + relu (+ post-relu scale), fp32 stores.
    #pragma unroll
    for (int mi = 0; mi < 2; mi++) {
        const int row = bm * 128 + warp_m * 32 + mi * 16 + grp;
        #pragma unroll
        for (int nb = 0; nb < 8; nb++) {
            const int col = bn * 128 + warp_n * 64 + nb * 8 + 2 * qid;
            float2 bz = *(const float2*)(bias + col);
            float2 o0, o1;
            o0.x = fmaxf(acc[mi][nb][0] + bz.x, 0.f) * scale;
            o0.y = fmaxf(acc[mi][nb][1] + bz.y, 0.f) * scale;
            o1.x = fmaxf(acc[mi][nb][2] + bz.x, 0.f) * scale;
            o1.y = fmaxf(acc[mi][nb][3] + bz.y, 0.f) * scale;
            *(float2*)(C + (size_t)row * HDIM + col) = o0;
            *(float2*)(C + (size_t)(row + 8) * HDIM + col) = o1;
        }
    }
}

// Fused K/V/Q GEMM: grid (2 n-tiles, 256 m-tiles, 3 planes).
__global__ void __launch_bounds__(256, 2) fused_mma_kernel(
    const float* __restrict__ social, const float* __restrict__ enc,
    const float* __restrict__ bk, const float* __restrict__ bv,
    const float* __restrict__ bq, float inv_sqrt_d, int qm_tiles)
{
    extern __shared__ char smraw[];
    const int z = blockIdx.z;
    if (z == 2) {
        if (blockIdx.y >= qm_tiles) return;
        gemm_tile_body(enc, g_wqt, bq, g_q, inv_sqrt_d, blockIdx.y, blockIdx.x, smraw);
    } else {
        gemm_tile_body(social, z ? g_wvt : g_wkt, z ? bv : bk, z ? g_v : g_k, 1.0f,
                       blockIdx.y, blockIdx.x, smraw);
    }
}

// ---------------------------------------------------------------------------
// Windowed attention. Score phase: unroll x2 over K rows (MLP 4).
// V phase: unroll x8, clamped rows, zero-padded weights (nn <= 63).
// ---------------------------------------------------------------------------
__global__ void __launch_bounds__(256) attn_kernel(
    const int* __restrict__ starts, const int* __restrict__ ends, float* __restrict__ out)
{
    const int i = blockIdx.x;
    const int tid = threadIdx.x;
    const int warp = tid >> 5, lane = tid & 31;
    __shared__ float qs[HDIM];
    __shared__ float sc[72];
    __shared__ float redbuf[8];

    qs[tid] = g_q[(size_t)i * HDIM + tid];
    if (tid < 72) sc[tid] = 0.f;
    const int s = starts[i];
    const int nn = ends[i] - s;   // 1..63
    __syncthreads();

    {
        const float4* qrow = (const float4*)qs + lane * 2;
        const float4 q0 = qrow[0], q1 = qrow[1];
        int j = warp;
        for (; j + 8 < nn; j += 16) {
            const float4* ka = (const float4*)(g_k + (size_t)(s + j) * HDIM) + lane * 2;
            const float4* kb = (const float4*)(g_k + (size_t)(s + j + 8) * HDIM) + lane * 2;
            float4 a0 = ka[0], a1 = ka[1];
            float4 b0 = kb[0], b1 = kb[1];
            float accA = a0.x * q0.x;
            float accB = b0.x * q0.x;
            accA = fmaf(a0.y, q0.y, accA);  accB = fmaf(b0.y, q0.y, accB);
            accA = fmaf(a0.z, q0.z, accA);  accB = fmaf(b0.z, q0.z, accB);
            accA = fmaf(a0.w, q0.w, accA);  accB = fmaf(b0.w, q0.w, accB);
            accA = fmaf(a1.x, q1.x, accA);  accB = fmaf(b1.x, q1.x, accB);
            accA = fmaf(a1.y, q1.y, accA);  accB = fmaf(b1.y, q1.y, accB);
            accA = fmaf(a1.z, q1.z, accA);  accB = fmaf(b1.z, q1.z, accB);
            accA = fmaf(a1.w, q1.w, accA);  accB = fmaf(b1.w, q1.w, accB);
            #pragma unroll
            for (int o = 16; o; o >>= 1) {
                accA += __shfl_xor_sync(0xffffffffu, accA, o);
                accB += __shfl_xor_sync(0xffffffffu, accB, o);
            }
            if (lane == 0) { sc[j] = accA; sc[j + 8] = accB; }
        }
        if (j < nn) {
            const float4* krow = (const float4*)(g_k + (size_t)(s + j) * HDIM) + lane * 2;
            float4 k0 = krow[0], k1 = krow[1];
            float acc = k0.x * q0.x;
            acc = fmaf(k0.y, q0.y, acc);
            acc = fmaf(k0.z, q0.z, acc);
            acc = fmaf(k0.w, q0.w, acc);
            acc = fmaf(k1.x, q1.x, acc);
            acc = fmaf(k1.y, q1.y, acc);
            acc = fmaf(k1.z, q1.z, acc);
            acc = fmaf(k1.w, q1.w, acc);
            #pragma unroll
            for (int o = 16; o; o >>= 1) acc += __shfl_xor_sync(0xffffffffu, acc, o);
            if (lane == 0) sc[j] = acc;
        }
    }
    __syncthreads();

    float x = -CUDART_INF_F;
    if (tid < 64) {
        x = (tid < nn) ? sc[tid] : -CUDART_INF_F;
        float m = x;
        #pragma unroll
        for (int o = 16; o; o >>= 1) m = fmaxf(m, __shfl_xor_sync(0xffffffffu, m, o));
        if (lane == 0) redbuf[warp] = m;
    }
    __syncthreads();
    const float m = fmaxf(redbuf[0], redbuf[1]);
    float p = 0.f;
    if (tid < 64) {
        p = (tid < nn) ? expf(x - m) : 0.f;
        float ssum = p;
        #pragma unroll
        for (int o = 16; o; o >>= 1) ssum += __shfl_xor_sync(0xffffffffu, ssum, o);
        if (lane == 0) redbuf[4 + warp] = ssum;
    }
    __syncthreads();
    const float inv = 1.f / (redbuf[4] + redbuf[5]);
    if (tid < 64) sc[tid] = p * inv;
    __syncthreads();

    const float* vbase = g_v + (size_t)s * HDIM + tid;
    const int jmax = nn - 1;
    float acc = 0.f;
    for (int j = 0; j < nn; j += 8) {
        float w[8], v[8];
        #pragma unroll
        for (int u = 0; u < 8; u++) {
            int jj = min(j + u, jmax);
            w[u] = sc[j + u];
            v[u] = vbase[(size_t)jj * HDIM];
        }
        #pragma unroll
        for (int u = 0; u < 8; u++) acc = fmaf(w[u], v[u], acc);
    }
    out[(size_t)i * HDIM + tid] = acc;
}

// ---------------------------------------------------------------------------
extern "C" void kernel_launch(void* const* d_in, const int* in_sizes, int n_in,
                              void* d_out, int out_size)
{
    const float* enc    = (const float*)d_in[0];
    const float* social = (const float*)d_in[1];
    const int*   starts = (const int*)  d_in[2];
    const int*   ends   = (const int*)  d_in[3];
    const float* Wq     = (const float*)d_in[4];
    const float* bq     = (const float*)d_in[5];
    const float* Wk     = (const float*)d_in[6];
    const float* bk     = (const float*)d_in[7];
    const float* Wv     = (const float*)d_in[8];
    const float* bv     = (const float*)d_in[9];
    float* out = (float*)d_out;

    const int B = in_sizes[0] / HDIM;
    const int N = in_sizes[1] / HDIM;

    __half *wk16, *wv16, *wq16;
    cudaGetSymbolAddress((void**)&wk16, g_wkt);
    cudaGetSymbolAddress((void**)&wv16, g_wvt);
    cudaGetSymbolAddress((void**)&wq16, g_wqt);

    cudaFuncSetAttribute(fused_mma_kernel, cudaFuncAttributeMaxDynamicSharedMemorySize, SMEM_BYTES);

    const float inv_sqrt_d = 1.0f / sqrtf((float)HDIM);

    // 1. Tiled transpose+convert Wk, Wv, Wq to fp16
    convert_w_kernel<<<dim3(HDIM / 32, HDIM / 32, 3), 256>>>(Wk, Wv, Wq, wk16, wv16, wq16);
    // 2. K, V and Q in ONE launch (z=0:K, z=1:V, z=2:Q)
    fused_mma_kernel<<<dim3(HDIM / 128, N / 128, 3), 256, SMEM_BYTES>>>(
        social, enc, bk, bv, bq, inv_sqrt_d, B / 128);
    // 3. Windowed attention
    attn_kernel<<<B, 256>>>(starts, ends, out);
}